// round 4
// baseline (speedup 1.0000x reference)
#include <cuda_runtime.h>
#include <stdint.h>

static constexpr int NN = 100000;
static constexpr int NE = 1600000;

// Scratch (device globals — no allocations allowed)
__device__ float g_dinv[NN];
__device__ float g_p[(size_t)NN * 128];
__device__ float g_h[(size_t)NN * 128];
__device__ int   g_cnt[NN];
__device__ int   g_rowptr[NN + 1];
__device__ int   g_cursor[NN];
__device__ int   g_col[NE];

// ---------------------------------------------------------------------------
// CSR build: histogram -> scan -> scatter
// edge_index is int32 [2][NE]: src = ei[e], dst = ei[NE + e]
// ---------------------------------------------------------------------------
__global__ void zero_cnt_kernel(int* __restrict__ cnt) {
    int i = blockIdx.x * blockDim.x + threadIdx.x;
    if (i < NN) cnt[i] = 0;
}

__global__ void hist_kernel(const int* __restrict__ ei,
                            int* __restrict__ cnt) {
    int e = blockIdx.x * blockDim.x + threadIdx.x;
    if (e < NE) atomicAdd(&cnt[ei[NE + e]], 1);
}

// Single block, 1024 threads: exclusive scan of cnt -> rowptr/cursor, dinv fused
__global__ __launch_bounds__(1024) void scan_kernel(
    const int* __restrict__ cnt, int* __restrict__ rowptr,
    int* __restrict__ cursor, float* __restrict__ dinv)
{
    __shared__ int sums[1024];
    const int t = threadIdx.x;
    const int chunk = (NN + 1023) / 1024;       // 98
    const int begin = t * chunk;
    const int end = (begin + chunk < NN) ? begin + chunk : NN;

    int s = 0;
    for (int i = begin; i < end; i++) s += cnt[i];
    sums[t] = s;
    __syncthreads();
    // Hillis-Steele inclusive scan
    for (int off = 1; off < 1024; off <<= 1) {
        int v = (t >= off) ? sums[t - off] : 0;
        __syncthreads();
        sums[t] += v;
        __syncthreads();
    }
    int run = (t == 0) ? 0 : sums[t - 1];
    for (int i = begin; i < end; i++) {
        rowptr[i] = run;
        cursor[i] = run;
        dinv[i] = rsqrtf((float)(cnt[i] + 1));   // +1 self loop
        run += cnt[i];
    }
    if (t == 1023) rowptr[NN] = sums[1023];
}

__global__ void build_kernel(const int* __restrict__ ei,
                             int* __restrict__ cursor,
                             int* __restrict__ col) {
    int e = blockIdx.x * blockDim.x + threadIdx.x;
    if (e < NE) {
        int s = ei[e];
        int d = ei[NE + e];
        col[atomicAdd(&cursor[d], 1)] = s;
    }
}

// ---------------------------------------------------------------------------
// Fused GEMM:  P[v,:] = (X[v,:] @ W) * dinv[v]
// ---------------------------------------------------------------------------
template <int COUT>
__global__ __launch_bounds__(256) void gemm_scale_kernel(
    const float* __restrict__ X, const float* __restrict__ W,
    const float* __restrict__ dinv, float* __restrict__ P)
{
    constexpr int TM = 64;
    constexpr int CT = COUT / 16;     // 8 or 4
    extern __shared__ float smem[];
    float* Xs = smem;                 // [64][129]
    float* Ws = smem + TM * 129;      // [128][COUT]

    const int tid = threadIdx.x;
    const int rowBase = blockIdx.x * TM;

    #pragma unroll
    for (int i = 0; i < (TM * 128) / 256; i++) {
        int idx = tid + i * 256;
        int r = idx >> 7, k = idx & 127;
        int gr = rowBase + r;
        Xs[r * 129 + k] = (gr < NN) ? X[(size_t)gr * 128 + k] : 0.0f;
    }
    #pragma unroll
    for (int i = 0; i < (128 * COUT) / (256 * 4); i++) {
        int idx = (tid + i * 256) * 4;
        *(float4*)&Ws[idx] = *(const float4*)&W[idx];
    }
    __syncthreads();

    const int col0 = (tid & 15) * CT;
    const int row0 = (tid >> 4) * 4;

    float acc[4][CT];
    #pragma unroll
    for (int i = 0; i < 4; i++)
        #pragma unroll
        for (int j = 0; j < CT; j++) acc[i][j] = 0.0f;

    #pragma unroll 4
    for (int k = 0; k < 128; k++) {
        float xv[4];
        #pragma unroll
        for (int i = 0; i < 4; i++) xv[i] = Xs[(row0 + i) * 129 + k];
        float wv[CT];
        #pragma unroll
        for (int j = 0; j < CT; j += 4)
            *(float4*)&wv[j] = *(const float4*)&Ws[k * COUT + col0 + j];
        #pragma unroll
        for (int i = 0; i < 4; i++)
            #pragma unroll
            for (int j = 0; j < CT; j++)
                acc[i][j] = fmaf(xv[i], wv[j], acc[i][j]);
    }

    #pragma unroll
    for (int i = 0; i < 4; i++) {
        int gr = rowBase + row0 + i;
        if (gr >= NN) continue;
        float dv = dinv[gr];
        #pragma unroll
        for (int j = 0; j < CT; j += 4) {
            float4 v = make_float4(acc[i][j + 0] * dv, acc[i][j + 1] * dv,
                                   acc[i][j + 2] * dv, acc[i][j + 3] * dv);
            *(float4*)&P[(size_t)gr * COUT + col0 + j] = v;
        }
    }
}

// ---------------------------------------------------------------------------
// Gather + finalize: one warp per node.
//   acc = P[v] + sum_{i in [rowptr[v],rowptr[v+1])} P[col[i]]
//   OUT[v] = act(dinv[v]*acc + b)
// ---------------------------------------------------------------------------
template <int COUT, bool RELU>
__global__ __launch_bounds__(256) void gather_kernel(
    const float* __restrict__ P, const int* __restrict__ rowptr,
    const int* __restrict__ col, const float* __restrict__ dinv,
    const float* __restrict__ bias, float* __restrict__ OUT)
{
    const int v = (int)((blockIdx.x * 256u + threadIdx.x) >> 5);
    const int lane = threadIdx.x & 31;
    if (v >= NN) return;

    const int start = __ldg(&rowptr[v]);
    const int end   = __ldg(&rowptr[v + 1]);

    if (COUT == 128) {
        const size_t off = (size_t)lane * 4;
        float4 acc = *(const float4*)(P + (size_t)v * 128 + off);  // self loop
        int i = start;
        for (; i + 1 < end; i += 2) {
            int s0 = __ldg(&col[i]);
            int s1 = __ldg(&col[i + 1]);
            float4 a = *(const float4*)(P + (size_t)s0 * 128 + off);
            float4 b = *(const float4*)(P + (size_t)s1 * 128 + off);
            acc.x += a.x; acc.y += a.y; acc.z += a.z; acc.w += a.w;
            acc.x += b.x; acc.y += b.y; acc.z += b.z; acc.w += b.w;
        }
        if (i < end) {
            int s0 = __ldg(&col[i]);
            float4 a = *(const float4*)(P + (size_t)s0 * 128 + off);
            acc.x += a.x; acc.y += a.y; acc.z += a.z; acc.w += a.w;
        }
        float dv = dinv[v];
        float4 bb = *(const float4*)(bias + off);
        float4 r = make_float4(fmaf(dv, acc.x, bb.x), fmaf(dv, acc.y, bb.y),
                               fmaf(dv, acc.z, bb.z), fmaf(dv, acc.w, bb.w));
        if (RELU) {
            r.x = fmaxf(r.x, 0.0f); r.y = fmaxf(r.y, 0.0f);
            r.z = fmaxf(r.z, 0.0f); r.w = fmaxf(r.w, 0.0f);
        }
        *(float4*)(OUT + (size_t)v * 128 + off) = r;
    } else {
        const size_t off = (size_t)lane * 2;
        float2 acc = *(const float2*)(P + (size_t)v * 64 + off);
        int i = start;
        for (; i + 1 < end; i += 2) {
            int s0 = __ldg(&col[i]);
            int s1 = __ldg(&col[i + 1]);
            float2 a = *(const float2*)(P + (size_t)s0 * 64 + off);
            float2 b = *(const float2*)(P + (size_t)s1 * 64 + off);
            acc.x += a.x; acc.y += a.y;
            acc.x += b.x; acc.y += b.y;
        }
        if (i < end) {
            int s0 = __ldg(&col[i]);
            float2 a = *(const float2*)(P + (size_t)s0 * 64 + off);
            acc.x += a.x; acc.y += a.y;
        }
        float dv = dinv[v];
        float2 bb = *(const float2*)(bias + off);
        float2 r = make_float2(fmaf(dv, acc.x, bb.x), fmaf(dv, acc.y, bb.y));
        if (RELU) { r.x = fmaxf(r.x, 0.0f); r.y = fmaxf(r.y, 0.0f); }
        *(float2*)(OUT + (size_t)v * 64 + off) = r;
    }
}

// ---------------------------------------------------------------------------
// Launch
// ---------------------------------------------------------------------------
extern "C" void kernel_launch(void* const* d_in, const int* in_sizes, int n_in,
                              void* d_out, int out_size) {
    const float* x  = (const float*)d_in[0];
    const int*   ei = (const int*)d_in[1];       // int32 [2][NE]
    const float* W1 = (const float*)d_in[2];
    const float* b1 = (const float*)d_in[3];
    const float* W2 = (const float*)d_in[4];
    const float* b2 = (const float*)d_in[5];
    const float* W3 = (const float*)d_in[6];
    const float* b3 = (const float*)d_in[7];
    float* out = (float*)d_out;

    float *dinv, *p, *h;
    int *cnt, *rowptr, *cursor, *col;
    cudaGetSymbolAddress((void**)&dinv,   g_dinv);
    cudaGetSymbolAddress((void**)&p,      g_p);
    cudaGetSymbolAddress((void**)&h,      g_h);
    cudaGetSymbolAddress((void**)&cnt,    g_cnt);
    cudaGetSymbolAddress((void**)&rowptr, g_rowptr);
    cudaGetSymbolAddress((void**)&cursor, g_cursor);
    cudaGetSymbolAddress((void**)&col,    g_col);

    constexpr int SMEM128 = (64 * 129 + 128 * 128) * 4;  // 98560 B
    constexpr int SMEM64  = (64 * 129 + 128 * 64) * 4;   // 65792 B
    cudaFuncSetAttribute(gemm_scale_kernel<128>,
                         cudaFuncAttributeMaxDynamicSharedMemorySize, SMEM128);
    cudaFuncSetAttribute(gemm_scale_kernel<64>,
                         cudaFuncAttributeMaxDynamicSharedMemorySize, SMEM64);

    const int TB = 256;
    const int nBlkN     = (NN + TB - 1) / TB;
    const int nBlkE     = (NE + TB - 1) / TB;
    const int gemmBlk   = (NN + 63) / 64;
    const int gatherBlk = (NN * 32 + TB - 1) / TB;   // one warp per node

    // CSR build + normalization
    zero_cnt_kernel<<<nBlkN, TB>>>(cnt);
    hist_kernel<<<nBlkE, TB>>>(ei, cnt);
    scan_kernel<<<1, 1024>>>(cnt, rowptr, cursor, dinv);
    build_kernel<<<nBlkE, TB>>>(ei, cursor, col);

    // layer 1
    gemm_scale_kernel<128><<<gemmBlk, TB, SMEM128>>>(x, W1, dinv, p);
    gather_kernel<128, true><<<gatherBlk, TB>>>(p, rowptr, col, dinv, b1, h);
    // layer 2
    gemm_scale_kernel<128><<<gemmBlk, TB, SMEM128>>>(h, W2, dinv, p);
    gather_kernel<128, true><<<gatherBlk, TB>>>(p, rowptr, col, dinv, b2, h);
    // layer 3
    gemm_scale_kernel<64><<<gemmBlk, TB, SMEM64>>>(h, W3, dinv, p);
    gather_kernel<64, false><<<gatherBlk, TB>>>(p, rowptr, col, dinv, b3, out);
}

// round 6
// speedup vs baseline: 1.1461x; 1.1461x over previous
#include <cuda_runtime.h>
#include <mma.h>
#include <stdint.h>

using namespace nvcuda;

static constexpr int NN = 100000;
static constexpr int NE = 1600000;

// Scratch (device globals — no allocations allowed)
__device__ float g_dinv[NN];
__device__ float g_p[(size_t)NN * 128];
__device__ float g_h[(size_t)NN * 128];
__device__ int   g_cnt[NN];
__device__ int   g_rowptr[NN + 1];
__device__ int   g_cursor[NN];
__device__ int   g_col[NE];

// ---------------------------------------------------------------------------
// CSR build: histogram -> scan -> scatter (edge_index int32 [2][NE])
// ---------------------------------------------------------------------------
__global__ void zero_cnt_kernel(int* __restrict__ cnt) {
    int i = blockIdx.x * blockDim.x + threadIdx.x;
    if (i < NN) cnt[i] = 0;
}

__global__ void hist_kernel(const int* __restrict__ ei, int* __restrict__ cnt) {
    int e = blockIdx.x * blockDim.x + threadIdx.x;
    if (e < NE) atomicAdd(&cnt[ei[NE + e]], 1);
}

__global__ __launch_bounds__(1024) void scan_kernel(
    const int* __restrict__ cnt, int* __restrict__ rowptr,
    int* __restrict__ cursor, float* __restrict__ dinv)
{
    __shared__ int sums[1024];
    const int t = threadIdx.x;
    const int chunk = (NN + 1023) / 1024;
    const int begin = t * chunk;
    const int end = (begin + chunk < NN) ? begin + chunk : NN;

    int s = 0;
    for (int i = begin; i < end; i++) s += cnt[i];
    sums[t] = s;
    __syncthreads();
    for (int off = 1; off < 1024; off <<= 1) {
        int v = (t >= off) ? sums[t - off] : 0;
        __syncthreads();
        sums[t] += v;
        __syncthreads();
    }
    int run = (t == 0) ? 0 : sums[t - 1];
    for (int i = begin; i < end; i++) {
        rowptr[i] = run;
        cursor[i] = run;
        dinv[i] = rsqrtf((float)(cnt[i] + 1));
        run += cnt[i];
    }
    if (t == 1023) rowptr[NN] = sums[1023];
}

__global__ void build_kernel(const int* __restrict__ ei,
                             int* __restrict__ cursor, int* __restrict__ col) {
    int e = blockIdx.x * blockDim.x + threadIdx.x;
    if (e < NE) {
        int s = ei[e];
        int d = ei[NE + e];
        col[atomicAdd(&cursor[d], 1)] = s;
    }
}

// ---------------------------------------------------------------------------
// wmma tf32 GEMM:  P[v,:] = X[v,:128] @ W[:128,:COUT]   (raw, no scaling)
// 256 threads = 8 warps; warp owns 16 rows x COUT cols. No SMEM.
// NN % 16 == 0 so warps are either fully valid or fully out of range.
// ---------------------------------------------------------------------------
template <int COUT>
__global__ __launch_bounds__(256) void gemm_wmma_kernel(
    const float* __restrict__ X, const float* __restrict__ W,
    float* __restrict__ P)
{
    constexpr int NT = COUT / 16;
    const int wid = threadIdx.x >> 5;
    const int m0 = blockIdx.x * 128 + wid * 16;
    if (m0 + 16 > NN) return;

    wmma::fragment<wmma::accumulator, 16, 16, 8, float> acc[NT];
    #pragma unroll
    for (int n = 0; n < NT; n++) wmma::fill_fragment(acc[n], 0.0f);

    #pragma unroll
    for (int k = 0; k < 128; k += 8) {
        wmma::fragment<wmma::matrix_a, 16, 16, 8, wmma::precision::tf32,
                       wmma::row_major> a;
        wmma::load_matrix_sync(a, X + (size_t)m0 * 128 + k, 128);
        #pragma unroll
        for (int i = 0; i < a.num_elements; i++)
            a.x[i] = wmma::__float_to_tf32(a.x[i]);

        #pragma unroll
        for (int n = 0; n < NT; n++) {
            wmma::fragment<wmma::matrix_b, 16, 16, 8, wmma::precision::tf32,
                           wmma::row_major> b;
            wmma::load_matrix_sync(b, W + (size_t)k * COUT + n * 16, COUT);
            #pragma unroll
            for (int i = 0; i < b.num_elements; i++)
                b.x[i] = wmma::__float_to_tf32(b.x[i]);
            wmma::mma_sync(acc[n], a, b, acc[n]);
        }
    }

    #pragma unroll
    for (int n = 0; n < NT; n++)
        wmma::store_matrix_sync(P + (size_t)m0 * COUT + n * 16, acc[n], COUT,
                                wmma::mem_row_major);
}

// ---------------------------------------------------------------------------
// Gather + finalize: one warp per node. P is raw H@W; norm applied here.
//   acc = dinv[v]*P[v] + sum_i dinv[col[i]] * P[col[i]]
//   OUT[v] = act(dinv[v]*acc + b)
// ---------------------------------------------------------------------------
template <int COUT, bool RELU>
__global__ __launch_bounds__(256) void gather_kernel(
    const float* __restrict__ P, const int* __restrict__ rowptr,
    const int* __restrict__ col, const float* __restrict__ dinv,
    const float* __restrict__ bias, float* __restrict__ OUT)
{
    const int v = (int)((blockIdx.x * 256u + threadIdx.x) >> 5);
    const int lane = threadIdx.x & 31;
    if (v >= NN) return;

    const int start = __ldg(&rowptr[v]);
    const int end   = __ldg(&rowptr[v + 1]);
    const float dvv = __ldg(&dinv[v]);

    if (COUT == 128) {
        const size_t off = (size_t)lane * 4;
        float4 sl = *(const float4*)(P + (size_t)v * 128 + off);
        float4 acc = make_float4(sl.x * dvv, sl.y * dvv, sl.z * dvv, sl.w * dvv);
        int i = start;
        for (; i + 3 < end; i += 4) {
            int s0 = __ldg(&col[i]);
            int s1 = __ldg(&col[i + 1]);
            int s2 = __ldg(&col[i + 2]);
            int s3 = __ldg(&col[i + 3]);
            float w0 = __ldg(&dinv[s0]);
            float w1 = __ldg(&dinv[s1]);
            float w2 = __ldg(&dinv[s2]);
            float w3 = __ldg(&dinv[s3]);
            float4 a = *(const float4*)(P + (size_t)s0 * 128 + off);
            float4 b = *(const float4*)(P + (size_t)s1 * 128 + off);
            float4 c = *(const float4*)(P + (size_t)s2 * 128 + off);
            float4 d = *(const float4*)(P + (size_t)s3 * 128 + off);
            acc.x = fmaf(w0, a.x, fmaf(w1, b.x, fmaf(w2, c.x, fmaf(w3, d.x, acc.x))));
            acc.y = fmaf(w0, a.y, fmaf(w1, b.y, fmaf(w2, c.y, fmaf(w3, d.y, acc.y))));
            acc.z = fmaf(w0, a.z, fmaf(w1, b.z, fmaf(w2, c.z, fmaf(w3, d.z, acc.z))));
            acc.w = fmaf(w0, a.w, fmaf(w1, b.w, fmaf(w2, c.w, fmaf(w3, d.w, acc.w))));
        }
        for (; i < end; i++) {
            int s0 = __ldg(&col[i]);
            float w0 = __ldg(&dinv[s0]);
            float4 a = *(const float4*)(P + (size_t)s0 * 128 + off);
            acc.x = fmaf(w0, a.x, acc.x);
            acc.y = fmaf(w0, a.y, acc.y);
            acc.z = fmaf(w0, a.z, acc.z);
            acc.w = fmaf(w0, a.w, acc.w);
        }
        float4 bb = *(const float4*)(bias + off);
        float4 r = make_float4(fmaf(dvv, acc.x, bb.x), fmaf(dvv, acc.y, bb.y),
                               fmaf(dvv, acc.z, bb.z), fmaf(dvv, acc.w, bb.w));
        if (RELU) {
            r.x = fmaxf(r.x, 0.0f); r.y = fmaxf(r.y, 0.0f);
            r.z = fmaxf(r.z, 0.0f); r.w = fmaxf(r.w, 0.0f);
        }
        *(float4*)(OUT + (size_t)v * 128 + off) = r;
    } else {
        const size_t off = (size_t)lane * 2;
        float2 sl = *(const float2*)(P + (size_t)v * 64 + off);
        float2 acc = make_float2(sl.x * dvv, sl.y * dvv);
        int i = start;
        for (; i + 3 < end; i += 4) {
            int s0 = __ldg(&col[i]);
            int s1 = __ldg(&col[i + 1]);
            int s2 = __ldg(&col[i + 2]);
            int s3 = __ldg(&col[i + 3]);
            float w0 = __ldg(&dinv[s0]);
            float w1 = __ldg(&dinv[s1]);
            float w2 = __ldg(&dinv[s2]);
            float w3 = __ldg(&dinv[s3]);
            float2 a = *(const float2*)(P + (size_t)s0 * 64 + off);
            float2 b = *(const float2*)(P + (size_t)s1 * 64 + off);
            float2 c = *(const float2*)(P + (size_t)s2 * 64 + off);
            float2 d = *(const float2*)(P + (size_t)s3 * 64 + off);
            acc.x = fmaf(w0, a.x, fmaf(w1, b.x, fmaf(w2, c.x, fmaf(w3, d.x, acc.x))));
            acc.y = fmaf(w0, a.y, fmaf(w1, b.y, fmaf(w2, c.y, fmaf(w3, d.y, acc.y))));
        }
        for (; i < end; i++) {
            int s0 = __ldg(&col[i]);
            float w0 = __ldg(&dinv[s0]);
            float2 a = *(const float2*)(P + (size_t)s0 * 64 + off);
            acc.x = fmaf(w0, a.x, acc.x);
            acc.y = fmaf(w0, a.y, acc.y);
        }
        float2 bb = *(const float2*)(bias + off);
        float2 r = make_float2(fmaf(dvv, acc.x, bb.x), fmaf(dvv, acc.y, bb.y));
        if (RELU) { r.x = fmaxf(r.x, 0.0f); r.y = fmaxf(r.y, 0.0f); }
        *(float2*)(OUT + (size_t)v * 64 + off) = r;
    }
}

// ---------------------------------------------------------------------------
// Launch
// ---------------------------------------------------------------------------
extern "C" void kernel_launch(void* const* d_in, const int* in_sizes, int n_in,
                              void* d_out, int out_size) {
    const float* x  = (const float*)d_in[0];
    const int*   ei = (const int*)d_in[1];
    const float* W1 = (const float*)d_in[2];
    const float* b1 = (const float*)d_in[3];
    const float* W2 = (const float*)d_in[4];
    const float* b2 = (const float*)d_in[5];
    const float* W3 = (const float*)d_in[6];
    const float* b3 = (const float*)d_in[7];
    float* out = (float*)d_out;

    float *dinv, *p, *h;
    int *cnt, *rowptr, *cursor, *col;
    cudaGetSymbolAddress((void**)&dinv,   g_dinv);
    cudaGetSymbolAddress((void**)&p,      g_p);
    cudaGetSymbolAddress((void**)&h,      g_h);
    cudaGetSymbolAddress((void**)&cnt,    g_cnt);
    cudaGetSymbolAddress((void**)&rowptr, g_rowptr);
    cudaGetSymbolAddress((void**)&cursor, g_cursor);
    cudaGetSymbolAddress((void**)&col,    g_col);

    const int TB = 256;
    const int nBlkN     = (NN + TB - 1) / TB;
    const int nBlkE     = (NE + TB - 1) / TB;
    const int gemmBlk   = (NN + 127) / 128;          // 782 (8 warps x 16 rows)
    const int gatherBlk = (NN * 32 + TB - 1) / TB;   // one warp per node

    // CSR build + normalization
    zero_cnt_kernel<<<nBlkN, TB>>>(cnt);
    hist_kernel<<<nBlkE, TB>>>(ei, cnt);
    scan_kernel<<<1, 1024>>>(cnt, rowptr, cursor, dinv);
    build_kernel<<<nBlkE, TB>>>(ei, cursor, col);

    // layer 1
    gemm_wmma_kernel<128><<<gemmBlk, TB>>>(x, W1, p);
    gather_kernel<128, true><<<gatherBlk, TB>>>(p, rowptr, col, dinv, b1, h);
    // layer 2
    gemm_wmma_kernel<128><<<gemmBlk, TB>>>(h, W2, p);
    gather_kernel<128, true><<<gatherBlk, TB>>>(p, rowptr, col, dinv, b2, h);
    // layer 3
    gemm_wmma_kernel<64><<<gemmBlk, TB>>>(h, W3, p);
    gather_kernel<64, false><<<gatherBlk, TB>>>(p, rowptr, col, dinv, b3, out);
}

// round 7
// speedup vs baseline: 1.2121x; 1.0576x over previous
#include <cuda_runtime.h>
#include <mma.h>
#include <stdint.h>

using namespace nvcuda;

static constexpr int NN = 100000;
static constexpr int NE = 1600000;

// Scratch (device globals — no allocations allowed)
__device__ float g_dinv[NN];
__device__ float g_xs[(size_t)NN * 128];   // pre-scaled layer-1 input
__device__ float g_p[(size_t)NN * 128];
__device__ float g_h[(size_t)NN * 128];
__device__ float g_w1t[128 * 128];
__device__ float g_w2t[128 * 128];
__device__ float g_w3t[128 * 64];
__device__ int   g_cnt[NN];
__device__ int   g_rowptr[NN + 1];
__device__ int   g_cursor[NN];
__device__ int   g_col[NE];

__device__ __forceinline__ uint32_t f32_to_tf32(float f) {
    uint32_t r;
    asm("cvt.rna.tf32.f32 %0, %1;" : "=r"(r) : "f"(f));
    return r;
}

// ---------------------------------------------------------------------------
// CSR build: histogram -> scan -> scatter (edge_index int32 [2][NE])
// ---------------------------------------------------------------------------
__global__ void zero_cnt_kernel(int* __restrict__ cnt) {
    int i = blockIdx.x * blockDim.x + threadIdx.x;
    if (i < NN) cnt[i] = 0;
}

__global__ void hist_kernel(const int* __restrict__ ei, int* __restrict__ cnt) {
    int e = blockIdx.x * blockDim.x + threadIdx.x;
    if (e < NE) atomicAdd(&cnt[ei[NE + e]], 1);
}

__global__ __launch_bounds__(1024) void scan_kernel(
    const int* __restrict__ cnt, int* __restrict__ rowptr,
    int* __restrict__ cursor, float* __restrict__ dinv)
{
    __shared__ int sums[1024];
    const int t = threadIdx.x;
    const int chunk = (NN + 1023) / 1024;
    const int begin = t * chunk;
    const int end = (begin + chunk < NN) ? begin + chunk : NN;

    int s = 0;
    for (int i = begin; i < end; i++) s += cnt[i];
    sums[t] = s;
    __syncthreads();
    for (int off = 1; off < 1024; off <<= 1) {
        int v = (t >= off) ? sums[t - off] : 0;
        __syncthreads();
        sums[t] += v;
        __syncthreads();
    }
    int run = (t == 0) ? 0 : sums[t - 1];
    for (int i = begin; i < end; i++) {
        rowptr[i] = run;
        cursor[i] = run;
        dinv[i] = rsqrtf((float)(cnt[i] + 1));
        run += cnt[i];
    }
    if (t == 1023) rowptr[NN] = sums[1023];
}

__global__ void build_kernel(const int* __restrict__ ei,
                             int* __restrict__ cursor, int* __restrict__ col) {
    int e = blockIdx.x * blockDim.x + threadIdx.x;
    if (e < NE) {
        int s = ei[e];
        int d = ei[NE + e];
        col[atomicAdd(&cursor[d], 1)] = s;
    }
}

// ---------------------------------------------------------------------------
// Prep: pre-round W to tf32 bits; pre-scale X by dinv[row]
// ---------------------------------------------------------------------------
__global__ void roundw_kernel(const float* __restrict__ W,
                              float* __restrict__ Wt, int n) {
    int i = blockIdx.x * blockDim.x + threadIdx.x;
    if (i < n) Wt[i] = __uint_as_float(f32_to_tf32(W[i]));
}

__global__ void xscale_kernel(const float* __restrict__ x,
                              const float* __restrict__ dinv,
                              float* __restrict__ xs) {
    int i = blockIdx.x * blockDim.x + threadIdx.x;   // float4 index
    if (i < NN * 32) {
        float4 v = ((const float4*)x)[i];
        float dv = __ldg(&dinv[i >> 5]);             // 32 float4 per row
        ((float4*)xs)[i] = make_float4(v.x * dv, v.y * dv, v.z * dv, v.w * dv);
    }
}

// ---------------------------------------------------------------------------
// wmma tf32 GEMM:  P = A @ Wt   (A pre-scaled by dinv; Wt pre-rounded tf32)
// 256 threads = 8 warps; warp tile = 32 rows x 64 cols.
// COUT=128: CTA = 128 rows x 128 cols (4 rg x 2 cg)
// COUT=64:  CTA = 256 rows x 64 cols  (8 rg x 1 cg)
// NN % 32 == 0, so warps are fully valid or fully out of range.
// ---------------------------------------------------------------------------
template <int COUT>
__global__ __launch_bounds__(256) void gemm_wmma_kernel(
    const float* __restrict__ A, const float* __restrict__ Wt,
    float* __restrict__ P)
{
    constexpr int CG = COUT / 64;          // col groups of warps
    constexpr int CTA_ROWS = (8 / CG) * 32;

    const int wid = threadIdx.x >> 5;
    const int cg = wid & (CG - 1);
    const int rg = wid / CG;
    const int m0 = blockIdx.x * CTA_ROWS + rg * 32;
    const int n0 = cg * 64;
    if (m0 + 32 > NN) return;

    wmma::fragment<wmma::accumulator, 16, 16, 8, float> acc[2][4];
    #pragma unroll
    for (int i = 0; i < 2; i++)
        #pragma unroll
        for (int j = 0; j < 4; j++) wmma::fill_fragment(acc[i][j], 0.0f);

    #pragma unroll
    for (int k = 0; k < 128; k += 8) {
        wmma::fragment<wmma::matrix_a, 16, 16, 8, wmma::precision::tf32,
                       wmma::row_major> a[2];
        #pragma unroll
        for (int i = 0; i < 2; i++) {
            wmma::load_matrix_sync(a[i], A + (size_t)(m0 + i * 16) * 128 + k, 128);
            #pragma unroll
            for (int t = 0; t < a[i].num_elements; t++)
                a[i].x[t] = wmma::__float_to_tf32(a[i].x[t]);
        }
        #pragma unroll
        for (int j = 0; j < 4; j++) {
            wmma::fragment<wmma::matrix_b, 16, 16, 8, wmma::precision::tf32,
                           wmma::row_major> b;
            // Wt already tf32-rounded: no per-element cvt needed
            wmma::load_matrix_sync(b, Wt + (size_t)k * COUT + n0 + j * 16, COUT);
            #pragma unroll
            for (int i = 0; i < 2; i++)
                wmma::mma_sync(acc[i][j], a[i], b, acc[i][j]);
        }
    }

    #pragma unroll
    for (int i = 0; i < 2; i++)
        #pragma unroll
        for (int j = 0; j < 4; j++)
            wmma::store_matrix_sync(P + (size_t)(m0 + i * 16) * COUT + n0 + j * 16,
                                    acc[i][j], COUT, wmma::mem_row_major);
}

// ---------------------------------------------------------------------------
// Gather + finalize: one warp per node. P rows already scaled by dinv[src].
//   acc = P[v] + sum_i P[col[i]]        (pure adds)
//   val = act(dinv[v]*acc + b)
//   OUT = SCALE_OUT ? dinv[v]*val : val   (pre-scale for next layer's GEMM)
// ---------------------------------------------------------------------------
template <int COUT, bool RELU, bool SCALE_OUT>
__global__ __launch_bounds__(256) void gather_kernel(
    const float* __restrict__ P, const int* __restrict__ rowptr,
    const int* __restrict__ col, const float* __restrict__ dinv,
    const float* __restrict__ bias, float* __restrict__ OUT)
{
    const int v = (int)((blockIdx.x * 256u + threadIdx.x) >> 5);
    const int lane = threadIdx.x & 31;
    if (v >= NN) return;

    const int start = __ldg(&rowptr[v]);
    const int end   = __ldg(&rowptr[v + 1]);
    const float dvv = __ldg(&dinv[v]);

    if (COUT == 128) {
        const size_t off = (size_t)lane * 4;
        float4 acc = *(const float4*)(P + (size_t)v * 128 + off);  // self loop
        int i = start;
        for (; i + 3 < end; i += 4) {
            int s0 = __ldg(&col[i]);
            int s1 = __ldg(&col[i + 1]);
            int s2 = __ldg(&col[i + 2]);
            int s3 = __ldg(&col[i + 3]);
            float4 a = *(const float4*)(P + (size_t)s0 * 128 + off);
            float4 b = *(const float4*)(P + (size_t)s1 * 128 + off);
            float4 c = *(const float4*)(P + (size_t)s2 * 128 + off);
            float4 d = *(const float4*)(P + (size_t)s3 * 128 + off);
            acc.x += (a.x + b.x) + (c.x + d.x);
            acc.y += (a.y + b.y) + (c.y + d.y);
            acc.z += (a.z + b.z) + (c.z + d.z);
            acc.w += (a.w + b.w) + (c.w + d.w);
        }
        for (; i < end; i++) {
            int s0 = __ldg(&col[i]);
            float4 a = *(const float4*)(P + (size_t)s0 * 128 + off);
            acc.x += a.x; acc.y += a.y; acc.z += a.z; acc.w += a.w;
        }
        float4 bb = *(const float4*)(bias + off);
        float4 r = make_float4(fmaf(dvv, acc.x, bb.x), fmaf(dvv, acc.y, bb.y),
                               fmaf(dvv, acc.z, bb.z), fmaf(dvv, acc.w, bb.w));
        if (RELU) {
            r.x = fmaxf(r.x, 0.0f); r.y = fmaxf(r.y, 0.0f);
            r.z = fmaxf(r.z, 0.0f); r.w = fmaxf(r.w, 0.0f);
        }
        if (SCALE_OUT) { r.x *= dvv; r.y *= dvv; r.z *= dvv; r.w *= dvv; }
        *(float4*)(OUT + (size_t)v * 128 + off) = r;
    } else {
        const size_t off = (size_t)lane * 2;
        float2 acc = *(const float2*)(P + (size_t)v * 64 + off);
        int i = start;
        for (; i + 3 < end; i += 4) {
            int s0 = __ldg(&col[i]);
            int s1 = __ldg(&col[i + 1]);
            int s2 = __ldg(&col[i + 2]);
            int s3 = __ldg(&col[i + 3]);
            float2 a = *(const float2*)(P + (size_t)s0 * 64 + off);
            float2 b = *(const float2*)(P + (size_t)s1 * 64 + off);
            float2 c = *(const float2*)(P + (size_t)s2 * 64 + off);
            float2 d = *(const float2*)(P + (size_t)s3 * 64 + off);
            acc.x += (a.x + b.x) + (c.x + d.x);
            acc.y += (a.y + b.y) + (c.y + d.y);
        }
        for (; i < end; i++) {
            int s0 = __ldg(&col[i]);
            float2 a = *(const float2*)(P + (size_t)s0 * 64 + off);
            acc.x += a.x; acc.y += a.y;
        }
        float2 bb = *(const float2*)(bias + off);
        float2 r = make_float2(fmaf(dvv, acc.x, bb.x), fmaf(dvv, acc.y, bb.y));
        if (RELU) { r.x = fmaxf(r.x, 0.0f); r.y = fmaxf(r.y, 0.0f); }
        if (SCALE_OUT) { r.x *= dvv; r.y *= dvv; }
        *(float2*)(OUT + (size_t)v * 64 + off) = r;
    }
}

// ---------------------------------------------------------------------------
// Launch
// ---------------------------------------------------------------------------
extern "C" void kernel_launch(void* const* d_in, const int* in_sizes, int n_in,
                              void* d_out, int out_size) {
    const float* x  = (const float*)d_in[0];
    const int*   ei = (const int*)d_in[1];
    const float* W1 = (const float*)d_in[2];
    const float* b1 = (const float*)d_in[3];
    const float* W2 = (const float*)d_in[4];
    const float* b2 = (const float*)d_in[5];
    const float* W3 = (const float*)d_in[6];
    const float* b3 = (const float*)d_in[7];
    float* out = (float*)d_out;

    float *dinv, *xs, *p, *h, *w1t, *w2t, *w3t;
    int *cnt, *rowptr, *cursor, *col;
    cudaGetSymbolAddress((void**)&dinv,   g_dinv);
    cudaGetSymbolAddress((void**)&xs,     g_xs);
    cudaGetSymbolAddress((void**)&p,      g_p);
    cudaGetSymbolAddress((void**)&h,      g_h);
    cudaGetSymbolAddress((void**)&w1t,    g_w1t);
    cudaGetSymbolAddress((void**)&w2t,    g_w2t);
    cudaGetSymbolAddress((void**)&w3t,    g_w3t);
    cudaGetSymbolAddress((void**)&cnt,    g_cnt);
    cudaGetSymbolAddress((void**)&rowptr, g_rowptr);
    cudaGetSymbolAddress((void**)&cursor, g_cursor);
    cudaGetSymbolAddress((void**)&col,    g_col);

    const int TB = 256;
    const int nBlkN      = (NN + TB - 1) / TB;
    const int nBlkE      = (NE + TB - 1) / TB;
    const int gemmBlk128 = (NN + 127) / 128;          // CTA = 128 rows
    const int gemmBlk64  = (NN + 255) / 256;          // CTA = 256 rows
    const int gatherBlk  = (NN * 32 + TB - 1) / TB;   // one warp per node
    const int xsBlk      = (NN * 32 + TB - 1) / TB;   // float4 elements

    // Weight pre-rounding (independent of everything else)
    roundw_kernel<<<(128 * 128 + TB - 1) / TB, TB>>>(W1, w1t, 128 * 128);
    roundw_kernel<<<(128 * 128 + TB - 1) / TB, TB>>>(W2, w2t, 128 * 128);
    roundw_kernel<<<(128 * 64 + TB - 1) / TB, TB>>>(W3, w3t, 128 * 64);

    // CSR build + normalization
    zero_cnt_kernel<<<nBlkN, TB>>>(cnt);
    hist_kernel<<<nBlkE, TB>>>(ei, cnt);
    scan_kernel<<<1, 1024>>>(cnt, rowptr, cursor, dinv);
    build_kernel<<<nBlkE, TB>>>(ei, cursor, col);

    // Pre-scale layer-1 input: xs = dinv[row] * x
    xscale_kernel<<<xsBlk, TB>>>(x, dinv, xs);

    // layer 1
    gemm_wmma_kernel<128><<<gemmBlk128, TB>>>(xs, w1t, p);
    gather_kernel<128, true, true><<<gatherBlk, TB>>>(p, rowptr, col, dinv, b1, h);
    // layer 2
    gemm_wmma_kernel<128><<<gemmBlk128, TB>>>(h, w2t, p);
    gather_kernel<128, true, true><<<gatherBlk, TB>>>(p, rowptr, col, dinv, b2, h);
    // layer 3
    gemm_wmma_kernel<64><<<gemmBlk64, TB>>>(h, w3t, p);
    gather_kernel<64, false, false><<<gatherBlk, TB>>>(p, rowptr, col, dinv, b3, out);
}

// round 8
// speedup vs baseline: 1.8268x; 1.5071x over previous
#include <cuda_runtime.h>
#include <mma.h>
#include <stdint.h>

using namespace nvcuda;

static constexpr int NN = 100000;
static constexpr int NE = 1600000;
static constexpr int SCAN_BLKS = (NN + 255) / 256;   // 391

// Scratch (device globals — no allocations allowed)
__device__ float g_dinv[NN];
__device__ float g_xs[(size_t)NN * 128];
__device__ float g_p[(size_t)NN * 128];
__device__ float g_h[(size_t)NN * 128];
__device__ float g_w1t[128 * 128];
__device__ float g_w2t[128 * 128];
__device__ float g_w3t[128 * 64];
__device__ int   g_cnt[NN];
__device__ int   g_bsum[SCAN_BLKS];
__device__ int   g_boff[SCAN_BLKS];
__device__ int   g_rowptr[NN + 1];
__device__ int   g_cursor[NN];
__device__ int   g_col[NE];

__device__ __forceinline__ uint32_t f32_to_tf32(float f) {
    uint32_t r;
    asm("cvt.rna.tf32.f32 %0, %1;" : "=r"(r) : "f"(f));
    return r;
}

// ---------------------------------------------------------------------------
// CSR build: histogram -> 3-phase coalesced scan -> scatter
// ---------------------------------------------------------------------------
__global__ void zero_cnt_kernel(int* __restrict__ cnt) {
    int i = blockIdx.x * blockDim.x + threadIdx.x;
    if (i < NN) cnt[i] = 0;
}

__global__ void hist_kernel(const int* __restrict__ ei, int* __restrict__ cnt) {
    int e = blockIdx.x * blockDim.x + threadIdx.x;
    if (e < NE) atomicAdd(&cnt[ei[NE + e]], 1);
}

// Phase 1: per-block sums (coalesced)
__global__ __launch_bounds__(256) void scan1_kernel(
    const int* __restrict__ cnt, int* __restrict__ bsum)
{
    __shared__ int warpsum[8];
    int idx = blockIdx.x * 256 + threadIdx.x;
    int c = (idx < NN) ? cnt[idx] : 0;
    int s = c;
    #pragma unroll
    for (int o = 16; o > 0; o >>= 1) s += __shfl_down_sync(0xFFFFFFFFu, s, o);
    if ((threadIdx.x & 31) == 0) warpsum[threadIdx.x >> 5] = s;
    __syncthreads();
    if (threadIdx.x < 8) {
        int t = warpsum[threadIdx.x];
        #pragma unroll
        for (int o = 4; o > 0; o >>= 1) t += __shfl_down_sync(0xFFu, t, o);
        if (threadIdx.x == 0) bsum[blockIdx.x] = t;
    }
}

// Phase 2: single block scans the 391 block sums -> exclusive offsets + total
__global__ __launch_bounds__(512) void scan2_kernel(
    const int* __restrict__ bsum, int* __restrict__ boff,
    int* __restrict__ rowptr)
{
    __shared__ int sh[512];
    int t = threadIdx.x;
    int v = (t < SCAN_BLKS) ? bsum[t] : 0;
    sh[t] = v;
    __syncthreads();
    #pragma unroll
    for (int o = 1; o < 512; o <<= 1) {
        int add = (t >= o) ? sh[t - o] : 0;
        __syncthreads();
        sh[t] += add;
        __syncthreads();
    }
    if (t < SCAN_BLKS) boff[t] = sh[t] - v;            // exclusive
    if (t == SCAN_BLKS - 1) rowptr[NN] = sh[t];        // total = NE
}

// Phase 3: per-block rescan + emit rowptr/cursor/dinv (coalesced)
__global__ __launch_bounds__(256) void scan3_kernel(
    const int* __restrict__ cnt, const int* __restrict__ boff,
    int* __restrict__ rowptr, int* __restrict__ cursor,
    float* __restrict__ dinv)
{
    __shared__ int warpincl[8];
    int idx = blockIdx.x * 256 + threadIdx.x;
    int lane = threadIdx.x & 31;
    int wid = threadIdx.x >> 5;
    int c = (idx < NN) ? cnt[idx] : 0;

    // warp inclusive scan
    int incl = c;
    #pragma unroll
    for (int o = 1; o < 32; o <<= 1) {
        int u = __shfl_up_sync(0xFFFFFFFFu, incl, o);
        if (lane >= o) incl += u;
    }
    if (lane == 31) warpincl[wid] = incl;
    __syncthreads();
    if (threadIdx.x < 8) {
        int u = warpincl[threadIdx.x];
        #pragma unroll
        for (int o = 1; o < 8; o <<= 1) {
            int w = __shfl_up_sync(0xFFu, u, o);
            if (threadIdx.x >= o) u += w;
        }
        warpincl[threadIdx.x] = u;
    }
    __syncthreads();
    int base = boff[blockIdx.x] + (wid > 0 ? warpincl[wid - 1] : 0);
    int excl = base + incl - c;
    if (idx < NN) {
        rowptr[idx] = excl;
        cursor[idx] = excl;
        dinv[idx] = rsqrtf((float)(c + 1));
    }
}

__global__ void build_kernel(const int* __restrict__ ei,
                             int* __restrict__ cursor, int* __restrict__ col) {
    int e = blockIdx.x * blockDim.x + threadIdx.x;
    if (e < NE) {
        int s = ei[e];
        int d = ei[NE + e];
        col[atomicAdd(&cursor[d], 1)] = s;
    }
}

// ---------------------------------------------------------------------------
// Prep: pre-round W to tf32 bits; pre-scale X by dinv[row]
// ---------------------------------------------------------------------------
__global__ void roundw_kernel(const float* __restrict__ W,
                              float* __restrict__ Wt, int n) {
    int i = blockIdx.x * blockDim.x + threadIdx.x;
    if (i < n) Wt[i] = __uint_as_float(f32_to_tf32(W[i]));
}

__global__ void xscale_kernel(const float* __restrict__ x,
                              const float* __restrict__ dinv,
                              float* __restrict__ xs) {
    int i = blockIdx.x * blockDim.x + threadIdx.x;   // float4 index
    if (i < NN * 32) {
        float4 v = ((const float4*)x)[i];
        float dv = __ldg(&dinv[i >> 5]);
        ((float4*)xs)[i] = make_float4(v.x * dv, v.y * dv, v.z * dv, v.w * dv);
    }
}

// ---------------------------------------------------------------------------
// wmma tf32 GEMM:  P = A @ Wt  (A pre-scaled; Wt pre-rounded tf32)
// 8 warps; warp tile = 32 rows x 64 cols.
// ---------------------------------------------------------------------------
template <int COUT>
__global__ __launch_bounds__(256) void gemm_wmma_kernel(
    const float* __restrict__ A, const float* __restrict__ Wt,
    float* __restrict__ P)
{
    constexpr int CG = COUT / 64;
    constexpr int CTA_ROWS = (8 / CG) * 32;

    const int wid = threadIdx.x >> 5;
    const int cg = wid & (CG - 1);
    const int rg = wid / CG;
    const int m0 = blockIdx.x * CTA_ROWS + rg * 32;
    const int n0 = cg * 64;
    if (m0 + 32 > NN) return;

    wmma::fragment<wmma::accumulator, 16, 16, 8, float> acc[2][4];
    #pragma unroll
    for (int i = 0; i < 2; i++)
        #pragma unroll
        for (int j = 0; j < 4; j++) wmma::fill_fragment(acc[i][j], 0.0f);

    #pragma unroll
    for (int k = 0; k < 128; k += 8) {
        wmma::fragment<wmma::matrix_a, 16, 16, 8, wmma::precision::tf32,
                       wmma::row_major> a[2];
        #pragma unroll
        for (int i = 0; i < 2; i++) {
            wmma::load_matrix_sync(a[i], A + (size_t)(m0 + i * 16) * 128 + k, 128);
            #pragma unroll
            for (int t = 0; t < a[i].num_elements; t++)
                a[i].x[t] = wmma::__float_to_tf32(a[i].x[t]);
        }
        #pragma unroll
        for (int j = 0; j < 4; j++) {
            wmma::fragment<wmma::matrix_b, 16, 16, 8, wmma::precision::tf32,
                           wmma::row_major> b;
            wmma::load_matrix_sync(b, Wt + (size_t)k * COUT + n0 + j * 16, COUT);
            #pragma unroll
            for (int i = 0; i < 2; i++)
                wmma::mma_sync(acc[i][j], a[i], b, acc[i][j]);
        }
    }

    #pragma unroll
    for (int i = 0; i < 2; i++)
        #pragma unroll
        for (int j = 0; j < 4; j++)
            wmma::store_matrix_sync(P + (size_t)(m0 + i * 16) * COUT + n0 + j * 16,
                                    acc[i][j], COUT, wmma::mem_row_major);
}

// ---------------------------------------------------------------------------
// Gather + finalize: one warp per node, 8-wide unrolled (P pre-scaled by src).
// ---------------------------------------------------------------------------
template <int COUT, bool RELU, bool SCALE_OUT>
__global__ __launch_bounds__(256) void gather_kernel(
    const float* __restrict__ P, const int* __restrict__ rowptr,
    const int* __restrict__ col, const float* __restrict__ dinv,
    const float* __restrict__ bias, float* __restrict__ OUT)
{
    const int v = (int)((blockIdx.x * 256u + threadIdx.x) >> 5);
    const int lane = threadIdx.x & 31;
    if (v >= NN) return;

    const int start = __ldg(&rowptr[v]);
    const int end   = __ldg(&rowptr[v + 1]);
    const float dvv = __ldg(&dinv[v]);

    if (COUT == 128) {
        const size_t off = (size_t)lane * 4;
        float4 acc = *(const float4*)(P + (size_t)v * 128 + off);  // self loop
        int i = start;
        for (; i + 7 < end; i += 8) {
            int s[8];
            #pragma unroll
            for (int u = 0; u < 8; u++) s[u] = __ldg(&col[i + u]);
            float4 t[8];
            #pragma unroll
            for (int u = 0; u < 8; u++)
                t[u] = *(const float4*)(P + (size_t)s[u] * 128 + off);
            float4 e0, e1;
            e0.x = (t[0].x + t[1].x) + (t[2].x + t[3].x);
            e0.y = (t[0].y + t[1].y) + (t[2].y + t[3].y);
            e0.z = (t[0].z + t[1].z) + (t[2].z + t[3].z);
            e0.w = (t[0].w + t[1].w) + (t[2].w + t[3].w);
            e1.x = (t[4].x + t[5].x) + (t[6].x + t[7].x);
            e1.y = (t[4].y + t[5].y) + (t[6].y + t[7].y);
            e1.z = (t[4].z + t[5].z) + (t[6].z + t[7].z);
            e1.w = (t[4].w + t[5].w) + (t[6].w + t[7].w);
            acc.x += e0.x + e1.x; acc.y += e0.y + e1.y;
            acc.z += e0.z + e1.z; acc.w += e0.w + e1.w;
        }
        for (; i + 3 < end; i += 4) {
            int s[4];
            #pragma unroll
            for (int u = 0; u < 4; u++) s[u] = __ldg(&col[i + u]);
            float4 t[4];
            #pragma unroll
            for (int u = 0; u < 4; u++)
                t[u] = *(const float4*)(P + (size_t)s[u] * 128 + off);
            acc.x += (t[0].x + t[1].x) + (t[2].x + t[3].x);
            acc.y += (t[0].y + t[1].y) + (t[2].y + t[3].y);
            acc.z += (t[0].z + t[1].z) + (t[2].z + t[3].z);
            acc.w += (t[0].w + t[1].w) + (t[2].w + t[3].w);
        }
        for (; i < end; i++) {
            int s0 = __ldg(&col[i]);
            float4 a = *(const float4*)(P + (size_t)s0 * 128 + off);
            acc.x += a.x; acc.y += a.y; acc.z += a.z; acc.w += a.w;
        }
        float4 bb = *(const float4*)(bias + off);
        float4 r = make_float4(fmaf(dvv, acc.x, bb.x), fmaf(dvv, acc.y, bb.y),
                               fmaf(dvv, acc.z, bb.z), fmaf(dvv, acc.w, bb.w));
        if (RELU) {
            r.x = fmaxf(r.x, 0.0f); r.y = fmaxf(r.y, 0.0f);
            r.z = fmaxf(r.z, 0.0f); r.w = fmaxf(r.w, 0.0f);
        }
        if (SCALE_OUT) { r.x *= dvv; r.y *= dvv; r.z *= dvv; r.w *= dvv; }
        *(float4*)(OUT + (size_t)v * 128 + off) = r;
    } else {
        const size_t off = (size_t)lane * 2;
        float2 acc = *(const float2*)(P + (size_t)v * 64 + off);
        int i = start;
        for (; i + 7 < end; i += 8) {
            int s[8];
            #pragma unroll
            for (int u = 0; u < 8; u++) s[u] = __ldg(&col[i + u]);
            float2 t[8];
            #pragma unroll
            for (int u = 0; u < 8; u++)
                t[u] = *(const float2*)(P + (size_t)s[u] * 64 + off);
            acc.x += ((t[0].x + t[1].x) + (t[2].x + t[3].x)) +
                     ((t[4].x + t[5].x) + (t[6].x + t[7].x));
            acc.y += ((t[0].y + t[1].y) + (t[2].y + t[3].y)) +
                     ((t[4].y + t[5].y) + (t[6].y + t[7].y));
        }
        for (; i + 3 < end; i += 4) {
            int s[4];
            #pragma unroll
            for (int u = 0; u < 4; u++) s[u] = __ldg(&col[i + u]);
            float2 t[4];
            #pragma unroll
            for (int u = 0; u < 4; u++)
                t[u] = *(const float2*)(P + (size_t)s[u] * 64 + off);
            acc.x += (t[0].x + t[1].x) + (t[2].x + t[3].x);
            acc.y += (t[0].y + t[1].y) + (t[2].y + t[3].y);
        }
        for (; i < end; i++) {
            int s0 = __ldg(&col[i]);
            float2 a = *(const float2*)(P + (size_t)s0 * 64 + off);
            acc.x += a.x; acc.y += a.y;
        }
        float2 bb = *(const float2*)(bias + off);
        float2 r = make_float2(fmaf(dvv, acc.x, bb.x), fmaf(dvv, acc.y, bb.y));
        if (RELU) { r.x = fmaxf(r.x, 0.0f); r.y = fmaxf(r.y, 0.0f); }
        if (SCALE_OUT) { r.x *= dvv; r.y *= dvv; }
        *(float2*)(OUT + (size_t)v * 64 + off) = r;
    }
}

// ---------------------------------------------------------------------------
// Launch
// ---------------------------------------------------------------------------
extern "C" void kernel_launch(void* const* d_in, const int* in_sizes, int n_in,
                              void* d_out, int out_size) {
    const float* x  = (const float*)d_in[0];
    const int*   ei = (const int*)d_in[1];
    const float* W1 = (const float*)d_in[2];
    const float* b1 = (const float*)d_in[3];
    const float* W2 = (const float*)d_in[4];
    const float* b2 = (const float*)d_in[5];
    const float* W3 = (const float*)d_in[6];
    const float* b3 = (const float*)d_in[7];
    float* out = (float*)d_out;

    float *dinv, *xs, *p, *h, *w1t, *w2t, *w3t;
    int *cnt, *bsum, *boff, *rowptr, *cursor, *col;
    cudaGetSymbolAddress((void**)&dinv,   g_dinv);
    cudaGetSymbolAddress((void**)&xs,     g_xs);
    cudaGetSymbolAddress((void**)&p,      g_p);
    cudaGetSymbolAddress((void**)&h,      g_h);
    cudaGetSymbolAddress((void**)&w1t,    g_w1t);
    cudaGetSymbolAddress((void**)&w2t,    g_w2t);
    cudaGetSymbolAddress((void**)&w3t,    g_w3t);
    cudaGetSymbolAddress((void**)&cnt,    g_cnt);
    cudaGetSymbolAddress((void**)&bsum,   g_bsum);
    cudaGetSymbolAddress((void**)&boff,   g_boff);
    cudaGetSymbolAddress((void**)&rowptr, g_rowptr);
    cudaGetSymbolAddress((void**)&cursor, g_cursor);
    cudaGetSymbolAddress((void**)&col,    g_col);

    const int TB = 256;
    const int nBlkN      = (NN + TB - 1) / TB;          // 391
    const int nBlkE      = (NE + TB - 1) / TB;
    const int gemmBlk128 = (NN + 127) / 128;
    const int gemmBlk64  = (NN + 255) / 256;
    const int gatherBlk  = (NN * 32 + TB - 1) / TB;
    const int xsBlk      = (NN * 32 + TB - 1) / TB;

    // Weight pre-rounding
    roundw_kernel<<<(128 * 128 + TB - 1) / TB, TB>>>(W1, w1t, 128 * 128);
    roundw_kernel<<<(128 * 128 + TB - 1) / TB, TB>>>(W2, w2t, 128 * 128);
    roundw_kernel<<<(128 * 64 + TB - 1) / TB, TB>>>(W3, w3t, 128 * 64);

    // CSR build + normalization (3-phase coalesced scan)
    zero_cnt_kernel<<<nBlkN, TB>>>(cnt);
    hist_kernel<<<nBlkE, TB>>>(ei, cnt);
    scan1_kernel<<<SCAN_BLKS, TB>>>(cnt, bsum);
    scan2_kernel<<<1, 512>>>(bsum, boff, rowptr);
    scan3_kernel<<<SCAN_BLKS, TB>>>(cnt, boff, rowptr, cursor, dinv);
    build_kernel<<<nBlkE, TB>>>(ei, cursor, col);

    // Pre-scale layer-1 input
    xscale_kernel<<<xsBlk, TB>>>(x, dinv, xs);

    // layer 1
    gemm_wmma_kernel<128><<<gemmBlk128, TB>>>(xs, w1t, p);
    gather_kernel<128, true, true><<<gatherBlk, TB>>>(p, rowptr, col, dinv, b1, h);
    // layer 2
    gemm_wmma_kernel<128><<<gemmBlk128, TB>>>(h, w2t, p);
    gather_kernel<128, true, true><<<gatherBlk, TB>>>(p, rowptr, col, dinv, b2, h);
    // layer 3
    gemm_wmma_kernel<64><<<gemmBlk64, TB>>>(h, w3t, p);
    gather_kernel<64, false, false><<<gatherBlk, TB>>>(p, rowptr, col, dinv, b3, out);
}

// round 10
// speedup vs baseline: 1.9122x; 1.0468x over previous
#include <cuda_runtime.h>
#include <cuda_fp16.h>
#include <mma.h>
#include <stdint.h>

using namespace nvcuda;

static constexpr int NN = 100000;
static constexpr int NE = 1600000;
static constexpr int SCAN_BLKS = (NN + 255) / 256;   // 391

// Scratch (device globals — no allocations allowed)
__device__ float  g_dinv[NN];
__device__ float  g_xs[(size_t)NN * 128];
__device__ __half g_p16[(size_t)NN * 128];
__device__ float  g_h[(size_t)NN * 128];
__device__ float  g_w1t[128 * 128];
__device__ float  g_w2t[128 * 128];
__device__ float  g_w3t[128 * 64];
__device__ int    g_cnt[NN];
__device__ int    g_bsum[SCAN_BLKS];
__device__ int    g_boff[SCAN_BLKS];
__device__ int    g_rowptr[NN + 1];
__device__ int    g_cursor[NN];
__device__ int    g_col[NE];

__device__ __forceinline__ uint32_t f32_to_tf32(float f) {
    uint32_t r;
    asm("cvt.rna.tf32.f32 %0, %1;" : "=r"(r) : "f"(f));
    return r;
}

// ---------------------------------------------------------------------------
// CSR build: histogram -> 3-phase coalesced scan -> scatter
// ---------------------------------------------------------------------------
__global__ void zero_cnt_kernel(int* __restrict__ cnt) {
    int i = blockIdx.x * blockDim.x + threadIdx.x;
    if (i < NN) cnt[i] = 0;
}

__global__ void hist_kernel(const int* __restrict__ ei, int* __restrict__ cnt) {
    int e = blockIdx.x * blockDim.x + threadIdx.x;
    if (e < NE) atomicAdd(&cnt[ei[NE + e]], 1);
}

__global__ __launch_bounds__(256) void scan1_kernel(
    const int* __restrict__ cnt, int* __restrict__ bsum)
{
    __shared__ int warpsum[8];
    int idx = blockIdx.x * 256 + threadIdx.x;
    int c = (idx < NN) ? cnt[idx] : 0;
    int s = c;
    #pragma unroll
    for (int o = 16; o > 0; o >>= 1) s += __shfl_down_sync(0xFFFFFFFFu, s, o);
    if ((threadIdx.x & 31) == 0) warpsum[threadIdx.x >> 5] = s;
    __syncthreads();
    if (threadIdx.x < 8) {
        int t = warpsum[threadIdx.x];
        #pragma unroll
        for (int o = 4; o > 0; o >>= 1) t += __shfl_down_sync(0xFFu, t, o);
        if (threadIdx.x == 0) bsum[blockIdx.x] = t;
    }
}

__global__ __launch_bounds__(512) void scan2_kernel(
    const int* __restrict__ bsum, int* __restrict__ boff,
    int* __restrict__ rowptr)
{
    __shared__ int sh[512];
    int t = threadIdx.x;
    int v = (t < SCAN_BLKS) ? bsum[t] : 0;
    sh[t] = v;
    __syncthreads();
    #pragma unroll
    for (int o = 1; o < 512; o <<= 1) {
        int add = (t >= o) ? sh[t - o] : 0;
        __syncthreads();
        sh[t] += add;
        __syncthreads();
    }
    if (t < SCAN_BLKS) boff[t] = sh[t] - v;
    if (t == SCAN_BLKS - 1) rowptr[NN] = sh[t];
}

__global__ __launch_bounds__(256) void scan3_kernel(
    const int* __restrict__ cnt, const int* __restrict__ boff,
    int* __restrict__ rowptr, int* __restrict__ cursor,
    float* __restrict__ dinv)
{
    __shared__ int warpincl[8];
    int idx = blockIdx.x * 256 + threadIdx.x;
    int lane = threadIdx.x & 31;
    int wid = threadIdx.x >> 5;
    int c = (idx < NN) ? cnt[idx] : 0;

    int incl = c;
    #pragma unroll
    for (int o = 1; o < 32; o <<= 1) {
        int u = __shfl_up_sync(0xFFFFFFFFu, incl, o);
        if (lane >= o) incl += u;
    }
    if (lane == 31) warpincl[wid] = incl;
    __syncthreads();
    if (threadIdx.x < 8) {
        int u = warpincl[threadIdx.x];
        #pragma unroll
        for (int o = 1; o < 8; o <<= 1) {
            int w = __shfl_up_sync(0xFFu, u, o);
            if (threadIdx.x >= o) u += w;
        }
        warpincl[threadIdx.x] = u;
    }
    __syncthreads();
    int base = boff[blockIdx.x] + (wid > 0 ? warpincl[wid - 1] : 0);
    int excl = base + incl - c;
    if (idx < NN) {
        rowptr[idx] = excl;
        cursor[idx] = excl;
        dinv[idx] = rsqrtf((float)(c + 1));
    }
}

__global__ void build_kernel(const int* __restrict__ ei,
                             int* __restrict__ cursor, int* __restrict__ col) {
    int e = blockIdx.x * blockDim.x + threadIdx.x;
    if (e < NE) {
        int s = ei[e];
        int d = ei[NE + e];
        col[atomicAdd(&cursor[d], 1)] = s;
    }
}

// ---------------------------------------------------------------------------
// Prep: pre-round W to tf32 bits; pre-scale X by dinv[row]
// ---------------------------------------------------------------------------
__global__ void roundw_kernel(const float* __restrict__ W,
                              float* __restrict__ Wt, int n) {
    int i = blockIdx.x * blockDim.x + threadIdx.x;
    if (i < n) Wt[i] = __uint_as_float(f32_to_tf32(W[i]));
}

__global__ void xscale_kernel(const float* __restrict__ x,
                              const float* __restrict__ dinv,
                              float* __restrict__ xs) {
    int i = blockIdx.x * blockDim.x + threadIdx.x;
    if (i < NN * 32) {
        float4 v = ((const float4*)x)[i];
        float dv = __ldg(&dinv[i >> 5]);
        ((float4*)xs)[i] = make_float4(v.x * dv, v.y * dv, v.z * dv, v.w * dv);
    }
}

// ---------------------------------------------------------------------------
// wmma tf32 GEMM:  P16 = half(A @ Wt)   (A pre-scaled fp32; Wt tf32 bits)
// 8 warps; warp tile = 32 rows x 64 cols. Epilogue via per-warp SMEM staging.
// ---------------------------------------------------------------------------
template <int COUT>
__global__ __launch_bounds__(256) void gemm_wmma_kernel(
    const float* __restrict__ A, const float* __restrict__ Wt,
    __half* __restrict__ P)
{
    constexpr int CG = COUT / 64;
    constexpr int CTA_ROWS = (8 / CG) * 32;

    __shared__ float stage[8][16 * 20];    // per-warp 16x16 tile, ldm=20

    const int wid = threadIdx.x >> 5;
    const int lane = threadIdx.x & 31;
    const int cg = wid & (CG - 1);
    const int rg = wid / CG;
    const int m0 = blockIdx.x * CTA_ROWS + rg * 32;
    const int n0 = cg * 64;
    if (m0 + 32 > NN) return;

    wmma::fragment<wmma::accumulator, 16, 16, 8, float> acc[2][4];
    #pragma unroll
    for (int i = 0; i < 2; i++)
        #pragma unroll
        for (int j = 0; j < 4; j++) wmma::fill_fragment(acc[i][j], 0.0f);

    #pragma unroll
    for (int k = 0; k < 128; k += 8) {
        wmma::fragment<wmma::matrix_a, 16, 16, 8, wmma::precision::tf32,
                       wmma::row_major> a[2];
        #pragma unroll
        for (int i = 0; i < 2; i++) {
            wmma::load_matrix_sync(a[i], A + (size_t)(m0 + i * 16) * 128 + k, 128);
            #pragma unroll
            for (int t = 0; t < a[i].num_elements; t++)
                a[i].x[t] = wmma::__float_to_tf32(a[i].x[t]);
        }
        #pragma unroll
        for (int j = 0; j < 4; j++) {
            wmma::fragment<wmma::matrix_b, 16, 16, 8, wmma::precision::tf32,
                           wmma::row_major> b;
            wmma::load_matrix_sync(b, Wt + (size_t)k * COUT + n0 + j * 16, COUT);
            #pragma unroll
            for (int i = 0; i < 2; i++)
                wmma::mma_sync(acc[i][j], a[i], b, acc[i][j]);
        }
    }

    // Epilogue: fp32 tile -> SMEM -> fp16 global (16B stores, 2 lanes/row)
    const int r = lane >> 1;
    const int c0 = (lane & 1) * 8;
    #pragma unroll
    for (int i = 0; i < 2; i++) {
        #pragma unroll
        for (int j = 0; j < 4; j++) {
            wmma::store_matrix_sync(&stage[wid][0], acc[i][j], 20,
                                    wmma::mem_row_major);
            __syncwarp();
            const float* s = &stage[wid][r * 20 + c0];
            __half2 h0 = __floats2half2_rn(s[0], s[1]);
            __half2 h1 = __floats2half2_rn(s[2], s[3]);
            __half2 h2 = __floats2half2_rn(s[4], s[5]);
            __half2 h3 = __floats2half2_rn(s[6], s[7]);
            uint4 pack;
            pack.x = *(uint32_t*)&h0;
            pack.y = *(uint32_t*)&h1;
            pack.z = *(uint32_t*)&h2;
            pack.w = *(uint32_t*)&h3;
            *(uint4*)(P + (size_t)(m0 + i * 16 + r) * COUT + n0 + j * 16 + c0) = pack;
            __syncwarp();
        }
    }
}

// ---------------------------------------------------------------------------
// Gather + finalize: one warp per node, 8-wide unrolled. P is fp16 (src-scaled).
//   acc = P[v] + sum_i P[col[i]];  val = act(dinv[v]*acc + b)
//   OUT (fp32) = SCALE_OUT ? dinv[v]*val : val
// ---------------------------------------------------------------------------
__device__ __forceinline__ void add_h4(float4& acc, uint2 u) {
    __half2 a = *(__half2*)&u.x;
    __half2 b = *(__half2*)&u.y;
    float2 fa = __half22float2(a);
    float2 fb = __half22float2(b);
    acc.x += fa.x; acc.y += fa.y; acc.z += fb.x; acc.w += fb.y;
}

template <int COUT, bool RELU, bool SCALE_OUT>
__global__ __launch_bounds__(256) void gather_kernel(
    const __half* __restrict__ P, const int* __restrict__ rowptr,
    const int* __restrict__ col, const float* __restrict__ dinv,
    const float* __restrict__ bias, float* __restrict__ OUT)
{
    const int v = (int)((blockIdx.x * 256u + threadIdx.x) >> 5);
    const int lane = threadIdx.x & 31;
    if (v >= NN) return;

    const int start = __ldg(&rowptr[v]);
    const int end   = __ldg(&rowptr[v + 1]);
    const float dvv = __ldg(&dinv[v]);

    if (COUT == 128) {
        const size_t off = (size_t)lane * 4;         // 4 halves per lane
        float4 acc = make_float4(0.f, 0.f, 0.f, 0.f);
        add_h4(acc, *(const uint2*)(P + (size_t)v * 128 + off));  // self loop
        int i = start;
        for (; i + 7 < end; i += 8) {
            int s[8];
            #pragma unroll
            for (int u = 0; u < 8; u++) s[u] = __ldg(&col[i + u]);
            uint2 t[8];
            #pragma unroll
            for (int u = 0; u < 8; u++)
                t[u] = *(const uint2*)(P + (size_t)s[u] * 128 + off);
            #pragma unroll
            for (int u = 0; u < 8; u++) add_h4(acc, t[u]);
        }
        for (; i + 3 < end; i += 4) {
            int s[4];
            #pragma unroll
            for (int u = 0; u < 4; u++) s[u] = __ldg(&col[i + u]);
            uint2 t[4];
            #pragma unroll
            for (int u = 0; u < 4; u++)
                t[u] = *(const uint2*)(P + (size_t)s[u] * 128 + off);
            #pragma unroll
            for (int u = 0; u < 4; u++) add_h4(acc, t[u]);
        }
        for (; i < end; i++) {
            int s0 = __ldg(&col[i]);
            add_h4(acc, *(const uint2*)(P + (size_t)s0 * 128 + off));
        }
        float4 bb = *(const float4*)(bias + off);
        float4 r = make_float4(fmaf(dvv, acc.x, bb.x), fmaf(dvv, acc.y, bb.y),
                               fmaf(dvv, acc.z, bb.z), fmaf(dvv, acc.w, bb.w));
        if (RELU) {
            r.x = fmaxf(r.x, 0.0f); r.y = fmaxf(r.y, 0.0f);
            r.z = fmaxf(r.z, 0.0f); r.w = fmaxf(r.w, 0.0f);
        }
        if (SCALE_OUT) { r.x *= dvv; r.y *= dvv; r.z *= dvv; r.w *= dvv; }
        *(float4*)(OUT + (size_t)v * 128 + off) = r;
    } else {
        const size_t off = (size_t)lane * 2;         // 2 halves per lane
        float2 acc = make_float2(0.f, 0.f);
        {
            __half2 hv = *(const __half2*)(P + (size_t)v * 64 + off);
            float2 f = __half22float2(hv);
            acc.x += f.x; acc.y += f.y;
        }
        int i = start;
        for (; i + 7 < end; i += 8) {
            int s[8];
            #pragma unroll
            for (int u = 0; u < 8; u++) s[u] = __ldg(&col[i + u]);
            __half2 t[8];
            #pragma unroll
            for (int u = 0; u < 8; u++)
                t[u] = *(const __half2*)(P + (size_t)s[u] * 64 + off);
            #pragma unroll
            for (int u = 0; u < 8; u++) {
                float2 f = __half22float2(t[u]);
                acc.x += f.x; acc.y += f.y;
            }
        }
        for (; i < end; i++) {
            int s0 = __ldg(&col[i]);
            float2 f = __half22float2(*(const __half2*)(P + (size_t)s0 * 64 + off));
            acc.x += f.x; acc.y += f.y;
        }
        float2 bb = *(const float2*)(bias + off);
        float2 r = make_float2(fmaf(dvv, acc.x, bb.x), fmaf(dvv, acc.y, bb.y));
        if (RELU) { r.x = fmaxf(r.x, 0.0f); r.y = fmaxf(r.y, 0.0f); }
        if (SCALE_OUT) { r.x *= dvv; r.y *= dvv; }
        *(float2*)(OUT + (size_t)v * 64 + off) = r;
    }
}

// ---------------------------------------------------------------------------
// Launch
// ---------------------------------------------------------------------------
extern "C" void kernel_launch(void* const* d_in, const int* in_sizes, int n_in,
                              void* d_out, int out_size) {
    const float* x  = (const float*)d_in[0];
    const int*   ei = (const int*)d_in[1];
    const float* W1 = (const float*)d_in[2];
    const float* b1 = (const float*)d_in[3];
    const float* W2 = (const float*)d_in[4];
    const float* b2 = (const float*)d_in[5];
    const float* W3 = (const float*)d_in[6];
    const float* b3 = (const float*)d_in[7];
    float* out = (float*)d_out;

    float *dinv, *xs, *h, *w1t, *w2t, *w3t;
    __half* p16;
    int *cnt, *bsum, *boff, *rowptr, *cursor, *col;
    cudaGetSymbolAddress((void**)&dinv,   g_dinv);
    cudaGetSymbolAddress((void**)&xs,     g_xs);
    cudaGetSymbolAddress((void**)&p16,    g_p16);
    cudaGetSymbolAddress((void**)&h,      g_h);
    cudaGetSymbolAddress((void**)&w1t,    g_w1t);
    cudaGetSymbolAddress((void**)&w2t,    g_w2t);
    cudaGetSymbolAddress((void**)&w3t,    g_w3t);
    cudaGetSymbolAddress((void**)&cnt,    g_cnt);
    cudaGetSymbolAddress((void**)&bsum,   g_bsum);
    cudaGetSymbolAddress((void**)&boff,   g_boff);
    cudaGetSymbolAddress((void**)&rowptr, g_rowptr);
    cudaGetSymbolAddress((void**)&cursor, g_cursor);
    cudaGetSymbolAddress((void**)&col,    g_col);

    const int TB = 256;
    const int nBlkN      = (NN + TB - 1) / TB;
    const int nBlkE      = (NE + TB - 1) / TB;
    const int gemmBlk128 = (NN + 127) / 128;
    const int gemmBlk64  = (NN + 255) / 256;
    const int gatherBlk  = (NN * 32 + TB - 1) / TB;
    const int xsBlk      = (NN * 32 + TB - 1) / TB;

    // Weight pre-rounding
    roundw_kernel<<<(128 * 128 + TB - 1) / TB, TB>>>(W1, w1t, 128 * 128);
    roundw_kernel<<<(128 * 128 + TB - 1) / TB, TB>>>(W2, w2t, 128 * 128);
    roundw_kernel<<<(128 * 64 + TB - 1) / TB, TB>>>(W3, w3t, 128 * 64);

    // CSR build + normalization
    zero_cnt_kernel<<<nBlkN, TB>>>(cnt);
    hist_kernel<<<nBlkE, TB>>>(ei, cnt);
    scan1_kernel<<<SCAN_BLKS, TB>>>(cnt, bsum);
    scan2_kernel<<<1, 512>>>(bsum, boff, rowptr);
    scan3_kernel<<<SCAN_BLKS, TB>>>(cnt, boff, rowptr, cursor, dinv);
    build_kernel<<<nBlkE, TB>>>(ei, cursor, col);

    // Pre-scale layer-1 input
    xscale_kernel<<<xsBlk, TB>>>(x, dinv, xs);

    // layer 1
    gemm_wmma_kernel<128><<<gemmBlk128, TB>>>(xs, w1t, p16);
    gather_kernel<128, true, true><<<gatherBlk, TB>>>(p16, rowptr, col, dinv, b1, h);
    // layer 2
    gemm_wmma_kernel<128><<<gemmBlk128, TB>>>(h, w2t, p16);
    gather_kernel<128, true, true><<<gatherBlk, TB>>>(p16, rowptr, col, dinv, b2, h);
    // layer 3
    gemm_wmma_kernel<64><<<gemmBlk64, TB>>>(h, w3t, p16);
    gather_kernel<64, false, false><<<gatherBlk, TB>>>(p16, rowptr, col, dinv, b3, out);
}

// round 11
// speedup vs baseline: 2.0492x; 1.0717x over previous
#include <cuda_runtime.h>
#include <cuda_fp16.h>
#include <mma.h>
#include <stdint.h>

using namespace nvcuda;

static constexpr int NN = 100000;
static constexpr int NE = 1600000;
static constexpr int SCAN_BLKS = (NN + 255) / 256;   // 391

// Scratch (device globals — no allocations allowed)
__device__ float  g_dinv[NN];
__device__ __half g_p16[(size_t)NN * 128];
__device__ float  g_h[(size_t)NN * 128];
__device__ float  g_w1t[128 * 128];
__device__ float  g_w2t[128 * 128];
__device__ float  g_w3t[128 * 64];
__device__ int    g_cnt[NN];
__device__ int    g_bsum[SCAN_BLKS];
__device__ int    g_boff[SCAN_BLKS];
__device__ int    g_rowptr[NN + 1];
__device__ int    g_cursor[NN];
__device__ int    g_col[NE];

__device__ __forceinline__ uint32_t f32_to_tf32(float f) {
    uint32_t r;
    asm("cvt.rna.tf32.f32 %0, %1;" : "=r"(r) : "f"(f));
    return r;
}

// ---------------------------------------------------------------------------
// CSR build: histogram -> 3-phase coalesced scan -> scatter
// ---------------------------------------------------------------------------
__global__ void zero_cnt_kernel(int* __restrict__ cnt) {
    int i = blockIdx.x * blockDim.x + threadIdx.x;
    if (i < NN) cnt[i] = 0;
}

__global__ void hist_kernel(const int* __restrict__ ei, int* __restrict__ cnt) {
    int e = blockIdx.x * blockDim.x + threadIdx.x;
    if (e < NE) atomicAdd(&cnt[ei[NE + e]], 1);
}

__global__ __launch_bounds__(256) void scan1_kernel(
    const int* __restrict__ cnt, int* __restrict__ bsum)
{
    __shared__ int warpsum[8];
    int idx = blockIdx.x * 256 + threadIdx.x;
    int c = (idx < NN) ? cnt[idx] : 0;
    int s = c;
    #pragma unroll
    for (int o = 16; o > 0; o >>= 1) s += __shfl_down_sync(0xFFFFFFFFu, s, o);
    if ((threadIdx.x & 31) == 0) warpsum[threadIdx.x >> 5] = s;
    __syncthreads();
    if (threadIdx.x < 8) {
        int t = warpsum[threadIdx.x];
        #pragma unroll
        for (int o = 4; o > 0; o >>= 1) t += __shfl_down_sync(0xFFu, t, o);
        if (threadIdx.x == 0) bsum[blockIdx.x] = t;
    }
}

__global__ __launch_bounds__(512) void scan2_kernel(
    const int* __restrict__ bsum, int* __restrict__ boff,
    int* __restrict__ rowptr)
{
    __shared__ int sh[512];
    int t = threadIdx.x;
    int v = (t < SCAN_BLKS) ? bsum[t] : 0;
    sh[t] = v;
    __syncthreads();
    #pragma unroll
    for (int o = 1; o < 512; o <<= 1) {
        int add = (t >= o) ? sh[t - o] : 0;
        __syncthreads();
        sh[t] += add;
        __syncthreads();
    }
    if (t < SCAN_BLKS) boff[t] = sh[t] - v;
    if (t == SCAN_BLKS - 1) rowptr[NN] = sh[t];
}

__global__ __launch_bounds__(256) void scan3_kernel(
    const int* __restrict__ cnt, const int* __restrict__ boff,
    int* __restrict__ rowptr, int* __restrict__ cursor,
    float* __restrict__ dinv)
{
    __shared__ int warpincl[8];
    int idx = blockIdx.x * 256 + threadIdx.x;
    int lane = threadIdx.x & 31;
    int wid = threadIdx.x >> 5;
    int c = (idx < NN) ? cnt[idx] : 0;

    int incl = c;
    #pragma unroll
    for (int o = 1; o < 32; o <<= 1) {
        int u = __shfl_up_sync(0xFFFFFFFFu, incl, o);
        if (lane >= o) incl += u;
    }
    if (lane == 31) warpincl[wid] = incl;
    __syncthreads();
    if (threadIdx.x < 8) {
        int u = warpincl[threadIdx.x];
        #pragma unroll
        for (int o = 1; o < 8; o <<= 1) {
            int w = __shfl_up_sync(0xFFu, u, o);
            if (threadIdx.x >= o) u += w;
        }
        warpincl[threadIdx.x] = u;
    }
    __syncthreads();
    int base = boff[blockIdx.x] + (wid > 0 ? warpincl[wid - 1] : 0);
    int excl = base + incl - c;
    if (idx < NN) {
        rowptr[idx] = excl;
        cursor[idx] = excl;
        dinv[idx] = rsqrtf((float)(c + 1));
    }
}

__global__ void build_kernel(const int* __restrict__ ei,
                             int* __restrict__ cursor, int* __restrict__ col) {
    int e = blockIdx.x * blockDim.x + threadIdx.x;
    if (e < NE) {
        int s = ei[e];
        int d = ei[NE + e];
        col[atomicAdd(&cursor[d], 1)] = s;
    }
}

// ---------------------------------------------------------------------------
// Prep: pre-round W to tf32 bits; scale P16 rows by dinv (post-join, layer 1)
// ---------------------------------------------------------------------------
__global__ void roundw_kernel(const float* __restrict__ W,
                              float* __restrict__ Wt, int n) {
    int i = blockIdx.x * blockDim.x + threadIdx.x;
    if (i < n) Wt[i] = __uint_as_float(f32_to_tf32(W[i]));
}

__global__ void pscale_kernel(__half* __restrict__ p,
                              const float* __restrict__ dinv) {
    int i = blockIdx.x * blockDim.x + threadIdx.x;   // uint4 = 8 halves
    if (i < NN * 16) {
        float dv = __ldg(&dinv[i >> 4]);             // 16 chunks per 128-row
        uint4 u = ((const uint4*)p)[i];
        __half2* h = (__half2*)&u;
        #pragma unroll
        for (int k = 0; k < 4; k++) {
            float2 f = __half22float2(h[k]);
            h[k] = __floats2half2_rn(f.x * dv, f.y * dv);
        }
        ((uint4*)p)[i] = u;
    }
}

// ---------------------------------------------------------------------------
// wmma tf32 GEMM:  P16 = half(A @ Wt)
// 8 warps; warp tile = 32 rows x 64 cols. Epilogue via per-warp SMEM staging.
// ---------------------------------------------------------------------------
template <int COUT>
__global__ __launch_bounds__(256) void gemm_wmma_kernel(
    const float* __restrict__ A, const float* __restrict__ Wt,
    __half* __restrict__ P)
{
    constexpr int CG = COUT / 64;
    constexpr int CTA_ROWS = (8 / CG) * 32;

    __shared__ float stage[8][16 * 20];

    const int wid = threadIdx.x >> 5;
    const int lane = threadIdx.x & 31;
    const int cg = wid & (CG - 1);
    const int rg = wid / CG;
    const int m0 = blockIdx.x * CTA_ROWS + rg * 32;
    const int n0 = cg * 64;
    if (m0 + 32 > NN) return;

    wmma::fragment<wmma::accumulator, 16, 16, 8, float> acc[2][4];
    #pragma unroll
    for (int i = 0; i < 2; i++)
        #pragma unroll
        for (int j = 0; j < 4; j++) wmma::fill_fragment(acc[i][j], 0.0f);

    #pragma unroll
    for (int k = 0; k < 128; k += 8) {
        wmma::fragment<wmma::matrix_a, 16, 16, 8, wmma::precision::tf32,
                       wmma::row_major> a[2];
        #pragma unroll
        for (int i = 0; i < 2; i++) {
            wmma::load_matrix_sync(a[i], A + (size_t)(m0 + i * 16) * 128 + k, 128);
            #pragma unroll
            for (int t = 0; t < a[i].num_elements; t++)
                a[i].x[t] = wmma::__float_to_tf32(a[i].x[t]);
        }
        #pragma unroll
        for (int j = 0; j < 4; j++) {
            wmma::fragment<wmma::matrix_b, 16, 16, 8, wmma::precision::tf32,
                           wmma::row_major> b;
            wmma::load_matrix_sync(b, Wt + (size_t)k * COUT + n0 + j * 16, COUT);
            #pragma unroll
            for (int i = 0; i < 2; i++)
                wmma::mma_sync(acc[i][j], a[i], b, acc[i][j]);
        }
    }

    const int r = lane >> 1;
    const int c0 = (lane & 1) * 8;
    #pragma unroll
    for (int i = 0; i < 2; i++) {
        #pragma unroll
        for (int j = 0; j < 4; j++) {
            wmma::store_matrix_sync(&stage[wid][0], acc[i][j], 20,
                                    wmma::mem_row_major);
            __syncwarp();
            const float* s = &stage[wid][r * 20 + c0];
            __half2 h0 = __floats2half2_rn(s[0], s[1]);
            __half2 h1 = __floats2half2_rn(s[2], s[3]);
            __half2 h2 = __floats2half2_rn(s[4], s[5]);
            __half2 h3 = __floats2half2_rn(s[6], s[7]);
            uint4 pack;
            pack.x = *(uint32_t*)&h0;
            pack.y = *(uint32_t*)&h1;
            pack.z = *(uint32_t*)&h2;
            pack.w = *(uint32_t*)&h3;
            *(uint4*)(P + (size_t)(m0 + i * 16 + r) * COUT + n0 + j * 16 + c0) = pack;
            __syncwarp();
        }
    }
}

// ---------------------------------------------------------------------------
// Gather + finalize: one warp per node, 8-wide unrolled. P fp16, src-scaled.
// ---------------------------------------------------------------------------
__device__ __forceinline__ void add_h4(float4& acc, uint2 u) {
    __half2 a = *(__half2*)&u.x;
    __half2 b = *(__half2*)&u.y;
    float2 fa = __half22float2(a);
    float2 fb = __half22float2(b);
    acc.x += fa.x; acc.y += fa.y; acc.z += fb.x; acc.w += fb.y;
}

template <int COUT, bool RELU, bool SCALE_OUT>
__global__ __launch_bounds__(256) void gather_kernel(
    const __half* __restrict__ P, const int* __restrict__ rowptr,
    const int* __restrict__ col, const float* __restrict__ dinv,
    const float* __restrict__ bias, float* __restrict__ OUT)
{
    const int v = (int)((blockIdx.x * 256u + threadIdx.x) >> 5);
    const int lane = threadIdx.x & 31;
    if (v >= NN) return;

    const int start = __ldg(&rowptr[v]);
    const int end   = __ldg(&rowptr[v + 1]);
    const float dvv = __ldg(&dinv[v]);

    if (COUT == 128) {
        const size_t off = (size_t)lane * 4;
        float4 acc = make_float4(0.f, 0.f, 0.f, 0.f);
        add_h4(acc, *(const uint2*)(P + (size_t)v * 128 + off));
        int i = start;
        for (; i + 7 < end; i += 8) {
            int s[8];
            #pragma unroll
            for (int u = 0; u < 8; u++) s[u] = __ldg(&col[i + u]);
            uint2 t[8];
            #pragma unroll
            for (int u = 0; u < 8; u++)
                t[u] = *(const uint2*)(P + (size_t)s[u] * 128 + off);
            #pragma unroll
            for (int u = 0; u < 8; u++) add_h4(acc, t[u]);
        }
        for (; i + 3 < end; i += 4) {
            int s[4];
            #pragma unroll
            for (int u = 0; u < 4; u++) s[u] = __ldg(&col[i + u]);
            uint2 t[4];
            #pragma unroll
            for (int u = 0; u < 4; u++)
                t[u] = *(const uint2*)(P + (size_t)s[u] * 128 + off);
            #pragma unroll
            for (int u = 0; u < 4; u++) add_h4(acc, t[u]);
        }
        for (; i < end; i++) {
            int s0 = __ldg(&col[i]);
            add_h4(acc, *(const uint2*)(P + (size_t)s0 * 128 + off));
        }
        float4 bb = *(const float4*)(bias + off);
        float4 r = make_float4(fmaf(dvv, acc.x, bb.x), fmaf(dvv, acc.y, bb.y),
                               fmaf(dvv, acc.z, bb.z), fmaf(dvv, acc.w, bb.w));
        if (RELU) {
            r.x = fmaxf(r.x, 0.0f); r.y = fmaxf(r.y, 0.0f);
            r.z = fmaxf(r.z, 0.0f); r.w = fmaxf(r.w, 0.0f);
        }
        if (SCALE_OUT) { r.x *= dvv; r.y *= dvv; r.z *= dvv; r.w *= dvv; }
        *(float4*)(OUT + (size_t)v * 128 + off) = r;
    } else {
        const size_t off = (size_t)lane * 2;
        float2 acc = make_float2(0.f, 0.f);
        {
            float2 f = __half22float2(*(const __half2*)(P + (size_t)v * 64 + off));
            acc.x += f.x; acc.y += f.y;
        }
        int i = start;
        for (; i + 7 < end; i += 8) {
            int s[8];
            #pragma unroll
            for (int u = 0; u < 8; u++) s[u] = __ldg(&col[i + u]);
            __half2 t[8];
            #pragma unroll
            for (int u = 0; u < 8; u++)
                t[u] = *(const __half2*)(P + (size_t)s[u] * 64 + off);
            #pragma unroll
            for (int u = 0; u < 8; u++) {
                float2 f = __half22float2(t[u]);
                acc.x += f.x; acc.y += f.y;
            }
        }
        for (; i < end; i++) {
            int s0 = __ldg(&col[i]);
            float2 f = __half22float2(*(const __half2*)(P + (size_t)s0 * 64 + off));
            acc.x += f.x; acc.y += f.y;
        }
        float2 bb = *(const float2*)(bias + off);
        float2 r = make_float2(fmaf(dvv, acc.x, bb.x), fmaf(dvv, acc.y, bb.y));
        if (RELU) { r.x = fmaxf(r.x, 0.0f); r.y = fmaxf(r.y, 0.0f); }
        if (SCALE_OUT) { r.x *= dvv; r.y *= dvv; }
        *(float2*)(OUT + (size_t)v * 64 + off) = r;
    }
}

// ---------------------------------------------------------------------------
// Launch — fork/join: CSR chain on default stream, W-prep + GEMM1 on side
// stream. Stream/event creation is host-side only (no device memory).
// ---------------------------------------------------------------------------
extern "C" void kernel_launch(void* const* d_in, const int* in_sizes, int n_in,
                              void* d_out, int out_size) {
    const float* x  = (const float*)d_in[0];
    const int*   ei = (const int*)d_in[1];
    const float* W1 = (const float*)d_in[2];
    const float* b1 = (const float*)d_in[3];
    const float* W2 = (const float*)d_in[4];
    const float* b2 = (const float*)d_in[5];
    const float* W3 = (const float*)d_in[6];
    const float* b3 = (const float*)d_in[7];
    float* out = (float*)d_out;

    float *dinv, *h, *w1t, *w2t, *w3t;
    __half* p16;
    int *cnt, *bsum, *boff, *rowptr, *cursor, *col;
    cudaGetSymbolAddress((void**)&dinv,   g_dinv);
    cudaGetSymbolAddress((void**)&p16,    g_p16);
    cudaGetSymbolAddress((void**)&h,      g_h);
    cudaGetSymbolAddress((void**)&w1t,    g_w1t);
    cudaGetSymbolAddress((void**)&w2t,    g_w2t);
    cudaGetSymbolAddress((void**)&w3t,    g_w3t);
    cudaGetSymbolAddress((void**)&cnt,    g_cnt);
    cudaGetSymbolAddress((void**)&bsum,   g_bsum);
    cudaGetSymbolAddress((void**)&boff,   g_boff);
    cudaGetSymbolAddress((void**)&rowptr, g_rowptr);
    cudaGetSymbolAddress((void**)&cursor, g_cursor);
    cudaGetSymbolAddress((void**)&col,    g_col);

    const int TB = 256;
    const int nBlkN      = (NN + TB - 1) / TB;
    const int nBlkE      = (NE + TB - 1) / TB;
    const int gemmBlk128 = (NN + 127) / 128;
    const int gemmBlk64  = (NN + 255) / 256;
    const int gatherBlk  = (NN * 32 + TB - 1) / TB;

    // Fork: side stream for W-prep + GEMM1 (independent of edge_index)
    cudaStream_t s2;
    cudaEvent_t eFork, eJoin;
    cudaStreamCreateWithFlags(&s2, cudaStreamNonBlocking);
    cudaEventCreateWithFlags(&eFork, cudaEventDisableTiming);
    cudaEventCreateWithFlags(&eJoin, cudaEventDisableTiming);

    cudaEventRecord(eFork, 0);
    cudaStreamWaitEvent(s2, eFork, 0);

    // side stream: weight prep + raw layer-1 GEMM
    roundw_kernel<<<(128 * 128 + TB - 1) / TB, TB, 0, s2>>>(W1, w1t, 128 * 128);
    roundw_kernel<<<(128 * 128 + TB - 1) / TB, TB, 0, s2>>>(W2, w2t, 128 * 128);
    roundw_kernel<<<(128 * 64 + TB - 1) / TB, TB, 0, s2>>>(W3, w3t, 128 * 64);
    gemm_wmma_kernel<128><<<gemmBlk128, TB, 0, s2>>>(x, w1t, p16);
    cudaEventRecord(eJoin, s2);

    // default stream: CSR build + normalization
    zero_cnt_kernel<<<nBlkN, TB>>>(cnt);
    hist_kernel<<<nBlkE, TB>>>(ei, cnt);
    scan1_kernel<<<SCAN_BLKS, TB>>>(cnt, bsum);
    scan2_kernel<<<1, 512>>>(bsum, boff, rowptr);
    scan3_kernel<<<SCAN_BLKS, TB>>>(cnt, boff, rowptr, cursor, dinv);
    build_kernel<<<nBlkE, TB>>>(ei, cursor, col);

    // join
    cudaStreamWaitEvent(0, eJoin, 0);

    // layer 1: scale P by dinv[row], then gather
    pscale_kernel<<<(NN * 16 + TB - 1) / TB, TB>>>(p16, dinv);
    gather_kernel<128, true, true><<<gatherBlk, TB>>>(p16, rowptr, col, dinv, b1, h);
    // layer 2
    gemm_wmma_kernel<128><<<gemmBlk128, TB>>>(h, w2t, p16);
    gather_kernel<128, true, true><<<gatherBlk, TB>>>(p16, rowptr, col, dinv, b2, h);
    // layer 3
    gemm_wmma_kernel<64><<<gemmBlk64, TB>>>(h, w3t, p16);
    gather_kernel<64, false, false><<<gatherBlk, TB>>>(p16, rowptr, col, dinv, b3, out);
}

// round 12
// speedup vs baseline: 2.3221x; 1.1331x over previous
#include <cuda_runtime.h>
#include <cuda_fp16.h>
#include <mma.h>
#include <stdint.h>

using namespace nvcuda;

static constexpr int NN = 100000;
static constexpr int NE = 1600000;
static constexpr int SCAN_BLKS = (NN + 255) / 256;   // 391

// Scratch (device globals — no allocations allowed)
__device__ float  g_dinv[NN];
__device__ __half g_x16[(size_t)NN * 128];
__device__ __half g_p16[(size_t)NN * 128];
__device__ __half g_h16[(size_t)NN * 128];
__device__ __half g_w1h[128 * 128];
__device__ __half g_w2h[128 * 128];
__device__ __half g_w3h[128 * 64];
__device__ int    g_cnt[NN];
__device__ int    g_bsum[SCAN_BLKS];
__device__ int    g_boff[SCAN_BLKS];
__device__ int    g_rowptr[NN + 1];
__device__ int    g_cursor[NN];
__device__ int    g_col[NE];

// ---------------------------------------------------------------------------
// CSR build: histogram -> 3-phase coalesced scan -> scatter
// ---------------------------------------------------------------------------
__global__ void zero_cnt_kernel(int* __restrict__ cnt) {
    int i = blockIdx.x * blockDim.x + threadIdx.x;
    if (i < NN) cnt[i] = 0;
}

__global__ void hist_kernel(const int* __restrict__ ei, int* __restrict__ cnt) {
    int e = blockIdx.x * blockDim.x + threadIdx.x;
    if (e < NE) atomicAdd(&cnt[ei[NE + e]], 1);
}

__global__ __launch_bounds__(256) void scan1_kernel(
    const int* __restrict__ cnt, int* __restrict__ bsum)
{
    __shared__ int warpsum[8];
    int idx = blockIdx.x * 256 + threadIdx.x;
    int c = (idx < NN) ? cnt[idx] : 0;
    int s = c;
    #pragma unroll
    for (int o = 16; o > 0; o >>= 1) s += __shfl_down_sync(0xFFFFFFFFu, s, o);
    if ((threadIdx.x & 31) == 0) warpsum[threadIdx.x >> 5] = s;
    __syncthreads();
    if (threadIdx.x < 8) {
        int t = warpsum[threadIdx.x];
        #pragma unroll
        for (int o = 4; o > 0; o >>= 1) t += __shfl_down_sync(0xFFu, t, o);
        if (threadIdx.x == 0) bsum[blockIdx.x] = t;
    }
}

__global__ __launch_bounds__(512) void scan2_kernel(
    const int* __restrict__ bsum, int* __restrict__ boff,
    int* __restrict__ rowptr)
{
    __shared__ int sh[512];
    int t = threadIdx.x;
    int v = (t < SCAN_BLKS) ? bsum[t] : 0;
    sh[t] = v;
    __syncthreads();
    #pragma unroll
    for (int o = 1; o < 512; o <<= 1) {
        int add = (t >= o) ? sh[t - o] : 0;
        __syncthreads();
        sh[t] += add;
        __syncthreads();
    }
    if (t < SCAN_BLKS) boff[t] = sh[t] - v;
    if (t == SCAN_BLKS - 1) rowptr[NN] = sh[t];
}

__global__ __launch_bounds__(256) void scan3_kernel(
    const int* __restrict__ cnt, const int* __restrict__ boff,
    int* __restrict__ rowptr, int* __restrict__ cursor,
    float* __restrict__ dinv)
{
    __shared__ int warpincl[8];
    int idx = blockIdx.x * 256 + threadIdx.x;
    int lane = threadIdx.x & 31;
    int wid = threadIdx.x >> 5;
    int c = (idx < NN) ? cnt[idx] : 0;

    int incl = c;
    #pragma unroll
    for (int o = 1; o < 32; o <<= 1) {
        int u = __shfl_up_sync(0xFFFFFFFFu, incl, o);
        if (lane >= o) incl += u;
    }
    if (lane == 31) warpincl[wid] = incl;
    __syncthreads();
    if (threadIdx.x < 8) {
        int u = warpincl[threadIdx.x];
        #pragma unroll
        for (int o = 1; o < 8; o <<= 1) {
            int w = __shfl_up_sync(0xFFu, u, o);
            if (threadIdx.x >= o) u += w;
        }
        warpincl[threadIdx.x] = u;
    }
    __syncthreads();
    int base = boff[blockIdx.x] + (wid > 0 ? warpincl[wid - 1] : 0);
    int excl = base + incl - c;
    if (idx < NN) {
        rowptr[idx] = excl;
        cursor[idx] = excl;
        dinv[idx] = rsqrtf((float)(c + 1));
    }
}

__global__ void build_kernel(const int* __restrict__ ei,
                             int* __restrict__ cursor, int* __restrict__ col) {
    int e = blockIdx.x * blockDim.x + threadIdx.x;
    if (e < NE) {
        int s = ei[e];
        int d = ei[NE + e];
        col[atomicAdd(&cursor[d], 1)] = s;
    }
}

// ---------------------------------------------------------------------------
// Prep: fp32 -> fp16 conversions; post-join P row scaling
// ---------------------------------------------------------------------------
__global__ void tohalf_kernel(const float* __restrict__ src,
                              __half* __restrict__ dst, int n4) {
    int i = blockIdx.x * blockDim.x + threadIdx.x;   // float4 index
    if (i < n4) {
        float4 v = ((const float4*)src)[i];
        __half2 h0 = __floats2half2_rn(v.x, v.y);
        __half2 h1 = __floats2half2_rn(v.z, v.w);
        uint2 pack;
        pack.x = *(uint32_t*)&h0;
        pack.y = *(uint32_t*)&h1;
        ((uint2*)dst)[i] = pack;
    }
}

__global__ void pscale_kernel(__half* __restrict__ p,
                              const float* __restrict__ dinv) {
    int i = blockIdx.x * blockDim.x + threadIdx.x;   // uint4 = 8 halves
    if (i < NN * 16) {
        float dv = __ldg(&dinv[i >> 4]);
        uint4 u = ((const uint4*)p)[i];
        __half2* h = (__half2*)&u;
        #pragma unroll
        for (int k = 0; k < 4; k++) {
            float2 f = __half22float2(h[k]);
            h[k] = __floats2half2_rn(f.x * dv, f.y * dv);
        }
        ((uint4*)p)[i] = u;
    }
}

// ---------------------------------------------------------------------------
// wmma fp16 GEMM (m16n16k16, fp32 accum):  P16 = half(A @ W)
// 8 warps; warp tile = 32 rows x 64 cols. Epilogue via per-warp SMEM staging.
// ---------------------------------------------------------------------------
template <int COUT>
__global__ __launch_bounds__(256) void gemm_wmma_kernel(
    const __half* __restrict__ A, const __half* __restrict__ W,
    __half* __restrict__ P)
{
    constexpr int CG = COUT / 64;
    constexpr int CTA_ROWS = (8 / CG) * 32;

    __shared__ float stage[8][16 * 20];

    const int wid = threadIdx.x >> 5;
    const int lane = threadIdx.x & 31;
    const int cg = wid & (CG - 1);
    const int rg = wid / CG;
    const int m0 = blockIdx.x * CTA_ROWS + rg * 32;
    const int n0 = cg * 64;
    if (m0 + 32 > NN) return;

    wmma::fragment<wmma::accumulator, 16, 16, 16, float> acc[2][4];
    #pragma unroll
    for (int i = 0; i < 2; i++)
        #pragma unroll
        for (int j = 0; j < 4; j++) wmma::fill_fragment(acc[i][j], 0.0f);

    #pragma unroll
    for (int k = 0; k < 128; k += 16) {
        wmma::fragment<wmma::matrix_a, 16, 16, 16, __half, wmma::row_major> a[2];
        #pragma unroll
        for (int i = 0; i < 2; i++)
            wmma::load_matrix_sync(a[i], A + (size_t)(m0 + i * 16) * 128 + k, 128);
        #pragma unroll
        for (int j = 0; j < 4; j++) {
            wmma::fragment<wmma::matrix_b, 16, 16, 16, __half, wmma::row_major> b;
            wmma::load_matrix_sync(b, W + (size_t)k * COUT + n0 + j * 16, COUT);
            #pragma unroll
            for (int i = 0; i < 2; i++)
                wmma::mma_sync(acc[i][j], a[i], b, acc[i][j]);
        }
    }

    const int r = lane >> 1;
    const int c0 = (lane & 1) * 8;
    #pragma unroll
    for (int i = 0; i < 2; i++) {
        #pragma unroll
        for (int j = 0; j < 4; j++) {
            wmma::store_matrix_sync(&stage[wid][0], acc[i][j], 20,
                                    wmma::mem_row_major);
            __syncwarp();
            const float* s = &stage[wid][r * 20 + c0];
            __half2 h0 = __floats2half2_rn(s[0], s[1]);
            __half2 h1 = __floats2half2_rn(s[2], s[3]);
            __half2 h2 = __floats2half2_rn(s[4], s[5]);
            __half2 h3 = __floats2half2_rn(s[6], s[7]);
            uint4 pack;
            pack.x = *(uint32_t*)&h0;
            pack.y = *(uint32_t*)&h1;
            pack.z = *(uint32_t*)&h2;
            pack.w = *(uint32_t*)&h3;
            *(uint4*)(P + (size_t)(m0 + i * 16 + r) * COUT + n0 + j * 16 + c0) = pack;
            __syncwarp();
        }
    }
}

// ---------------------------------------------------------------------------
// Gather + finalize: one warp per node, 8-wide unrolled. P fp16, src-scaled.
// HALF_OUT layers emit fp16 (next GEMM input); final layer emits fp32.
// ---------------------------------------------------------------------------
__device__ __forceinline__ void add_h4(float4& acc, uint2 u) {
    __half2 a = *(__half2*)&u.x;
    __half2 b = *(__half2*)&u.y;
    float2 fa = __half22float2(a);
    float2 fb = __half22float2(b);
    acc.x += fa.x; acc.y += fa.y; acc.z += fb.x; acc.w += fb.y;
}

template <int COUT, bool RELU, bool SCALE_OUT, bool HALF_OUT>
__global__ __launch_bounds__(256) void gather_kernel(
    const __half* __restrict__ P, const int* __restrict__ rowptr,
    const int* __restrict__ col, const float* __restrict__ dinv,
    const float* __restrict__ bias, void* __restrict__ OUT)
{
    const int v = (int)((blockIdx.x * 256u + threadIdx.x) >> 5);
    const int lane = threadIdx.x & 31;
    if (v >= NN) return;

    const int start = __ldg(&rowptr[v]);
    const int end   = __ldg(&rowptr[v + 1]);
    const float dvv = __ldg(&dinv[v]);

    if (COUT == 128) {
        const size_t off = (size_t)lane * 4;
        float4 acc = make_float4(0.f, 0.f, 0.f, 0.f);
        add_h4(acc, *(const uint2*)(P + (size_t)v * 128 + off));
        int i = start;
        for (; i + 7 < end; i += 8) {
            int s[8];
            #pragma unroll
            for (int u = 0; u < 8; u++) s[u] = __ldg(&col[i + u]);
            uint2 t[8];
            #pragma unroll
            for (int u = 0; u < 8; u++)
                t[u] = *(const uint2*)(P + (size_t)s[u] * 128 + off);
            #pragma unroll
            for (int u = 0; u < 8; u++) add_h4(acc, t[u]);
        }
        for (; i + 3 < end; i += 4) {
            int s[4];
            #pragma unroll
            for (int u = 0; u < 4; u++) s[u] = __ldg(&col[i + u]);
            uint2 t[4];
            #pragma unroll
            for (int u = 0; u < 4; u++)
                t[u] = *(const uint2*)(P + (size_t)s[u] * 128 + off);
            #pragma unroll
            for (int u = 0; u < 4; u++) add_h4(acc, t[u]);
        }
        for (; i < end; i++) {
            int s0 = __ldg(&col[i]);
            add_h4(acc, *(const uint2*)(P + (size_t)s0 * 128 + off));
        }
        float4 bb = *(const float4*)(bias + off);
        float4 r = make_float4(fmaf(dvv, acc.x, bb.x), fmaf(dvv, acc.y, bb.y),
                               fmaf(dvv, acc.z, bb.z), fmaf(dvv, acc.w, bb.w));
        if (RELU) {
            r.x = fmaxf(r.x, 0.0f); r.y = fmaxf(r.y, 0.0f);
            r.z = fmaxf(r.z, 0.0f); r.w = fmaxf(r.w, 0.0f);
        }
        if (SCALE_OUT) { r.x *= dvv; r.y *= dvv; r.z *= dvv; r.w *= dvv; }
        if (HALF_OUT) {
            __half2 h0 = __floats2half2_rn(r.x, r.y);
            __half2 h1 = __floats2half2_rn(r.z, r.w);
            uint2 pack;
            pack.x = *(uint32_t*)&h0;
            pack.y = *(uint32_t*)&h1;
            *(uint2*)((__half*)OUT + (size_t)v * 128 + off) = pack;
        } else {
            *(float4*)((float*)OUT + (size_t)v * 128 + off) = r;
        }
    } else {
        const size_t off = (size_t)lane * 2;
        float2 acc = make_float2(0.f, 0.f);
        {
            float2 f = __half22float2(*(const __half2*)(P + (size_t)v * 64 + off));
            acc.x += f.x; acc.y += f.y;
        }
        int i = start;
        for (; i + 7 < end; i += 8) {
            int s[8];
            #pragma unroll
            for (int u = 0; u < 8; u++) s[u] = __ldg(&col[i + u]);
            __half2 t[8];
            #pragma unroll
            for (int u = 0; u < 8; u++)
                t[u] = *(const __half2*)(P + (size_t)s[u] * 64 + off);
            #pragma unroll
            for (int u = 0; u < 8; u++) {
                float2 f = __half22float2(t[u]);
                acc.x += f.x; acc.y += f.y;
            }
        }
        for (; i < end; i++) {
            int s0 = __ldg(&col[i]);
            float2 f = __half22float2(*(const __half2*)(P + (size_t)s0 * 64 + off));
            acc.x += f.x; acc.y += f.y;
        }
        float2 bb = *(const float2*)(bias + off);
        float2 r = make_float2(fmaf(dvv, acc.x, bb.x), fmaf(dvv, acc.y, bb.y));
        if (RELU) { r.x = fmaxf(r.x, 0.0f); r.y = fmaxf(r.y, 0.0f); }
        if (SCALE_OUT) { r.x *= dvv; r.y *= dvv; }
        if (HALF_OUT) {
            __half2 h = __floats2half2_rn(r.x, r.y);
            *(__half2*)((__half*)OUT + (size_t)v * 64 + off) = h;
        } else {
            *(float2*)((float*)OUT + (size_t)v * 64 + off) = r;
        }
    }
}

// ---------------------------------------------------------------------------
// Launch — fork/join: CSR chain on default stream, prep + GEMM1 on side stream
// ---------------------------------------------------------------------------
extern "C" void kernel_launch(void* const* d_in, const int* in_sizes, int n_in,
                              void* d_out, int out_size) {
    const float* x  = (const float*)d_in[0];
    const int*   ei = (const int*)d_in[1];
    const float* W1 = (const float*)d_in[2];
    const float* b1 = (const float*)d_in[3];
    const float* W2 = (const float*)d_in[4];
    const float* b2 = (const float*)d_in[5];
    const float* W3 = (const float*)d_in[6];
    const float* b3 = (const float*)d_in[7];
    float* out = (float*)d_out;

    float *dinv;
    __half *x16, *p16, *h16, *w1h, *w2h, *w3h;
    int *cnt, *bsum, *boff, *rowptr, *cursor, *col;
    cudaGetSymbolAddress((void**)&dinv,   g_dinv);
    cudaGetSymbolAddress((void**)&x16,    g_x16);
    cudaGetSymbolAddress((void**)&p16,    g_p16);
    cudaGetSymbolAddress((void**)&h16,    g_h16);
    cudaGetSymbolAddress((void**)&w1h,    g_w1h);
    cudaGetSymbolAddress((void**)&w2h,    g_w2h);
    cudaGetSymbolAddress((void**)&w3h,    g_w3h);
    cudaGetSymbolAddress((void**)&cnt,    g_cnt);
    cudaGetSymbolAddress((void**)&bsum,   g_bsum);
    cudaGetSymbolAddress((void**)&boff,   g_boff);
    cudaGetSymbolAddress((void**)&rowptr, g_rowptr);
    cudaGetSymbolAddress((void**)&cursor, g_cursor);
    cudaGetSymbolAddress((void**)&col,    g_col);

    const int TB = 256;
    const int nBlkN      = (NN + TB - 1) / TB;
    const int nBlkE      = (NE + TB - 1) / TB;
    const int gemmBlk128 = (NN + 127) / 128;
    const int gemmBlk64  = (NN + 255) / 256;
    const int gatherBlk  = (NN * 32 + TB - 1) / TB;

    cudaStream_t s2;
    cudaEvent_t eFork, eJoin;
    cudaStreamCreateWithFlags(&s2, cudaStreamNonBlocking);
    cudaEventCreateWithFlags(&eFork, cudaEventDisableTiming);
    cudaEventCreateWithFlags(&eJoin, cudaEventDisableTiming);

    cudaEventRecord(eFork, 0);
    cudaStreamWaitEvent(s2, eFork, 0);

    // side stream: fp16 prep + raw layer-1 GEMM (independent of edge_index)
    tohalf_kernel<<<(128 * 128 / 4 + TB - 1) / TB, TB, 0, s2>>>(W1, w1h, 128 * 128 / 4);
    tohalf_kernel<<<(128 * 128 / 4 + TB - 1) / TB, TB, 0, s2>>>(W2, w2h, 128 * 128 / 4);
    tohalf_kernel<<<(128 * 64 / 4 + TB - 1) / TB, TB, 0, s2>>>(W3, w3h, 128 * 64 / 4);
    tohalf_kernel<<<(NN * 32 + TB - 1) / TB, TB, 0, s2>>>(x, x16, NN * 32);
    gemm_wmma_kernel<128><<<gemmBlk128, TB, 0, s2>>>(x16, w1h, p16);
    cudaEventRecord(eJoin, s2);

    // default stream: CSR build + normalization
    zero_cnt_kernel<<<nBlkN, TB>>>(cnt);
    hist_kernel<<<nBlkE, TB>>>(ei, cnt);
    scan1_kernel<<<SCAN_BLKS, TB>>>(cnt, bsum);
    scan2_kernel<<<1, 512>>>(bsum, boff, rowptr);
    scan3_kernel<<<SCAN_BLKS, TB>>>(cnt, boff, rowptr, cursor, dinv);
    build_kernel<<<nBlkE, TB>>>(ei, cursor, col);

    // join
    cudaStreamWaitEvent(0, eJoin, 0);

    // layer 1: scale P by dinv[row], then gather (emit fp16 h)
    pscale_kernel<<<(NN * 16 + TB - 1) / TB, TB>>>(p16, dinv);
    gather_kernel<128, true, true, true><<<gatherBlk, TB>>>(
        p16, rowptr, col, dinv, b1, h16);
    // layer 2
    gemm_wmma_kernel<128><<<gemmBlk128, TB>>>(h16, w2h, p16);
    gather_kernel<128, true, true, true><<<gatherBlk, TB>>>(
        p16, rowptr, col, dinv, b2, h16);
    // layer 3
    gemm_wmma_kernel<64><<<gemmBlk64, TB>>>(h16, w3h, p16);
    gather_kernel<64, false, false, false><<<gatherBlk, TB>>>(
        p16, rowptr, col, dinv, b3, out);
}